// round 3
// baseline (speedup 1.0000x reference)
#include <cuda_runtime.h>
#include <math.h>

#define G    12
#define H    8
#define CQK  32
#define CVAL 32
#define CIN  64
#define COUT 64
#define BATCH 2
#define SEQ  512
#define T_TOK (BATCH*SEQ)   // 1024 tokens
#define DIN  (G*CIN)        // 768
#define DQK  (G*H*CQK)      // 3072
#define GH   (G*H)          // 96

// ---------------- scratch (device globals; no allocation allowed) ----------
__device__ float g_q [T_TOK*DQK];
__device__ float g_k [T_TOK*DQK];
__device__ float g_v [T_TOK*DQK];
__device__ float g_qT[T_TOK*DQK];   // [b][gh][n][32]
__device__ float g_kT[T_TOK*DQK];
__device__ float g_vT[T_TOK*DQK];
__device__ float g_ao[T_TOK*DQK];   // attention out, token-major [t][gh*32+d]

// ---------------- block-circulant GEMM ------------------------------------
// Y[t][go*CO+o] = sum_{gi,i} X[t][gi*CI+i] * W[(gi-go)%G][o][i]
// Tiles: BM=64 tokens, BN=64 outputs, BK=32.  BK<=CI, BN<=CO and tiles are
// aligned, so each (k-tile, n-tile) touches exactly one (gi, go) pair.
template<int CO, int CI>
__global__ void __launch_bounds__(256) circ_gemm(const float* __restrict__ X,
                                                 const float* __restrict__ W,
                                                 float* __restrict__ Y)
{
    const int Ktot = G * CI;
    const int Ntot = G * CO;
    __shared__ float As[32][68];   // [k][token], padded row (16B-aligned rows)
    __shared__ float Bs[32][68];   // [k][out]

    const int tid = threadIdx.x;
    const int n0 = blockIdx.x * 64;
    const int t0 = blockIdx.y * 64;
    const int go = n0 / CO;
    const int o0 = n0 % CO;

    const int kl    = tid & 31;   // 0..31 (coalesced k / i)
    const int rbase = tid >> 5;   // 0..7
    const int tx = tid & 15;      // output micro-tile
    const int ty = tid >> 4;      // token  micro-tile

    float acc[4][4];
    #pragma unroll
    for (int i = 0; i < 4; i++)
        #pragma unroll
        for (int j = 0; j < 4; j++) acc[i][j] = 0.0f;

    for (int kk = 0; kk < Ktot; kk += 32) {
        const int gi = kk / CI;
        const int i0 = kk % CI;
        const int wg = (gi - go + G) % G;
        const float* Wb = W + ((size_t)wg * CO + o0) * CI + i0 + kl;
        const float* Xb = X + (size_t)t0 * Ktot + kk + kl;
        #pragma unroll
        for (int r = 0; r < 8; r++) {
            int row = rbase + r * 8;             // 0..63
            As[kl][row] = Xb[(size_t)row * Ktot];
            Bs[kl][row] = Wb[(size_t)row * CI];
        }
        __syncthreads();
        #pragma unroll
        for (int kr = 0; kr < 32; kr++) {
            float4 a = *(const float4*)&As[kr][ty * 4];
            float4 b = *(const float4*)&Bs[kr][tx * 4];
            float av[4] = {a.x, a.y, a.z, a.w};
            float bv[4] = {b.x, b.y, b.z, b.w};
            #pragma unroll
            for (int i = 0; i < 4; i++)
                #pragma unroll
                for (int j = 0; j < 4; j++)
                    acc[i][j] += av[i] * bv[j];
        }
        __syncthreads();
    }

    #pragma unroll
    for (int i = 0; i < 4; i++) {
        float4 o = make_float4(acc[i][0], acc[i][1], acc[i][2], acc[i][3]);
        *(float4*)&Y[(size_t)(t0 + ty * 4 + i) * Ntot + n0 + tx * 4] = o;
    }
}

// ---------------- rms_norm + sequence rope + platonic rope + transpose ----
// The two pair-rotations (sequence rope, platonic rope) compose into a single
// rotation by (seq_angle + platonic_phase).
__global__ void __launch_bounds__(256) rope_kernel(
    const float* __restrict__ coords, const int* __restrict__ seq_idx,
    const float* __restrict__ qnw, const float* __restrict__ knw,
    const float* __restrict__ pfreqs)
{
    const int t = blockIdx.x;
    const int b = t / SEQ, n = t % SEQ;
    const float cx = coords[t * 3 + 0];
    const float cy = coords[t * 3 + 1];
    const float cz = coords[t * 3 + 2];
    const float pos = (float)seq_idx[t];
    const float EPS = 1.1920929e-07f;                 // finfo(f32).eps
    const float LOG1E4_OV16 = 9.210340371976184f / 16.0f;

    for (int base = 0; base < GH * 16; base += 256) {
        const int p  = base + threadIdx.x;            // pair index, always <1536
        const int gh = p >> 4;
        const int f  = p & 15;
        const int g  = gh >> 3;
        const int h  = gh & 7;

        const int off = t * DQK + gh * 32 + 2 * f;
        float q1 = g_q[off], q2 = g_q[off + 1];
        float k1 = g_k[off], k2 = g_k[off + 1];

        // head-level sum of squares across the 16 lanes of this head
        float sq = q1 * q1 + q2 * q2;
        float sk = k1 * k1 + k2 * k2;
        #pragma unroll
        for (int o2 = 8; o2 > 0; o2 >>= 1) {
            sq += __shfl_xor_sync(0xffffffffu, sq, o2, 16);
            sk += __shfl_xor_sync(0xffffffffu, sk, o2, 16);
        }
        const float rq = rsqrtf(sq * (1.0f / 32.0f) + EPS);
        const float rk = rsqrtf(sk * (1.0f / 32.0f) + EPS);
        q1 *= rq * qnw[2 * f];  q2 *= rq * qnw[2 * f + 1];
        k1 *= rk * knw[2 * f];  k2 *= rk * knw[2 * f + 1];

        // sequence rope angle
        const float invf = expf(-(float)f * LOG1E4_OV16);
        const float ang  = pos * invf;

        // platonic phase: coords rotated about z by 2*pi*g/12, dotted with freqs[h][f]
        const float th = 6.283185307179586f * (float)g * (1.0f / 12.0f);
        float sg, cg;  sincosf(th, &sg, &cg);
        const float c0 =  cx * cg + cy * sg;
        const float c1 = -cx * sg + cy * cg;
        const float* fr = pfreqs + (h * 16 + f) * 3;
        const float ph  = c0 * fr[0] + c1 * fr[1] + cz * fr[2];

        float s, c;  sincosf(ang + ph, &s, &c);
        const float qo1 = q1 * c - q2 * s, qo2 = q1 * s + q2 * c;
        const float ko1 = k1 * c - k2 * s, ko2 = k1 * s + k2 * c;

        const size_t dst = (((size_t)b * GH + gh) * SEQ + n) * 32 + 2 * f;
        g_qT[dst] = qo1;  g_qT[dst + 1] = qo2;
        g_kT[dst] = ko1;  g_kT[dst + 1] = ko2;
    }

    // V transpose: token-major -> head-major
    for (int i = threadIdx.x; i < DQK; i += 256) {
        const int gh = i >> 5, d = i & 31;
        g_vT[(((size_t)b * GH + gh) * SEQ + n) * 32 + d] = g_v[(size_t)t * DQK + i];
    }
}

// ---------------- attention ------------------------------------------------
// One block per (b, head, chunk of 256 queries). Full K and V for the head
// live in 128 KB dynamic smem; every lane reads the same K/V row (broadcast
// LDS.128), thread owns one query. Two passes: max, then exp+accumulate.
// 256 threads/block -> 8 warps resident per SM (smem limits to 1 block/SM).
__global__ void __launch_bounds__(256) attn_kernel()
{
    extern __shared__ float sh[];
    float* Ks = sh;              // 512*32
    float* Vs = sh + SEQ * 32;   // 512*32

    const int qc = blockIdx.x;   // 0..1
    const int gh = blockIdx.y;   // 0..95
    const int b  = blockIdx.z;   // 0..1

    const size_t base = (((size_t)b * GH + gh) * SEQ) * 32;
    {
        const float4* kg = (const float4*)(g_kT + base);
        const float4* vg = (const float4*)(g_vT + base);
        float4* ks4 = (float4*)Ks;
        float4* vs4 = (float4*)Vs;
        for (int i = threadIdx.x; i < SEQ * 8; i += 256) {
            ks4[i] = kg[i];
            vs4[i] = vg[i];
        }
    }
    __syncthreads();

    const int n = qc * 256 + threadIdx.x;   // query index, always < 512
    float4 q[8];
    {
        const float4* qg = (const float4*)(g_qT + base + (size_t)n * 32);
        #pragma unroll
        for (int i = 0; i < 8; i++) q[i] = qg[i];
    }
    const float scale = 0.17677669529663687f;   // 1/sqrt(32)

    // pass 1: row max
    float m = -1e30f;
    for (int j = 0; j < SEQ; j++) {
        const float4* kp = (const float4*)(Ks + j * 32);
        float s = 0.0f;
        #pragma unroll
        for (int i = 0; i < 8; i++) {
            float4 kv = kp[i];
            s += q[i].x * kv.x + q[i].y * kv.y + q[i].z * kv.z + q[i].w * kv.w;
        }
        m = fmaxf(m, s * scale);
    }

    // pass 2: exp-sum + weighted V accumulate (scores recomputed; identical fp ops)
    float l = 0.0f;
    float4 acc[8];
    #pragma unroll
    for (int i = 0; i < 8; i++) acc[i] = make_float4(0.f, 0.f, 0.f, 0.f);
    for (int j = 0; j < SEQ; j++) {
        const float4* kp = (const float4*)(Ks + j * 32);
        float s = 0.0f;
        #pragma unroll
        for (int i = 0; i < 8; i++) {
            float4 kv = kp[i];
            s += q[i].x * kv.x + q[i].y * kv.y + q[i].z * kv.z + q[i].w * kv.w;
        }
        const float p = expf(s * scale - m);
        l += p;
        const float4* vp = (const float4*)(Vs + j * 32);
        #pragma unroll
        for (int i = 0; i < 8; i++) {
            float4 vv = vp[i];
            acc[i].x += p * vv.x;  acc[i].y += p * vv.y;
            acc[i].z += p * vv.z;  acc[i].w += p * vv.w;
        }
    }

    const float inv = 1.0f / l;
    float4* og = (float4*)(g_ao + ((size_t)(b * SEQ + n)) * DQK + gh * 32);
    #pragma unroll
    for (int i = 0; i < 8; i++) {
        float4 o = acc[i];
        o.x *= inv;  o.y *= inv;  o.z *= inv;  o.w *= inv;
        og[i] = o;
    }
}

// ---------------- launch ---------------------------------------------------
extern "C" void kernel_launch(void* const* d_in, const int* in_sizes, int n_in,
                              void* d_out, int out_size)
{
    const float* feat   = (const float*)d_in[0];
    const float* coords = (const float*)d_in[1];
    const float* Wq     = (const float*)d_in[2];
    const float* Wk     = (const float*)d_in[3];
    const float* Wv     = (const float*)d_in[4];
    const float* Wo     = (const float*)d_in[5];
    const float* qnw    = (const float*)d_in[6];
    const float* knw    = (const float*)d_in[7];
    const float* pfrq   = (const float*)d_in[8];
    const int*   sidx   = (const int*)d_in[9];
    float* out = (float*)d_out;

    void *pq, *pk, *pv, *pao;
    cudaGetSymbolAddress(&pq,  g_q);
    cudaGetSymbolAddress(&pk,  g_k);
    cudaGetSymbolAddress(&pv,  g_v);
    cudaGetSymbolAddress(&pao, g_ao);

    // QKV projections: M=1024 tokens x N=3072 outputs (K=768)
    dim3 gqkv(DQK / 64, T_TOK / 64);
    circ_gemm<H * CQK, CIN><<<gqkv, 256>>>(feat, Wq, (float*)pq);
    circ_gemm<H * CQK, CIN><<<gqkv, 256>>>(feat, Wk, (float*)pk);
    circ_gemm<H * CVAL, CIN><<<gqkv, 256>>>(feat, Wv, (float*)pv);

    // norm + ropes + transpose
    rope_kernel<<<T_TOK, 256>>>(coords, sidx, qnw, knw, pfrq);

    // attention (128 KB dynamic smem: opt-in required)
    cudaFuncSetAttribute(attn_kernel,
                         cudaFuncAttributeMaxDynamicSharedMemorySize, 131072);
    attn_kernel<<<dim3(2, GH, BATCH), 256, 131072>>>();

    // output projection: M=1024 x N=768 (K=3072), writes d_out directly
    dim3 go(G * COUT / 64, T_TOK / 64);
    circ_gemm<COUT, H * CVAL><<<go, 256>>>((const float*)pao, Wo, out);
}

// round 4
// speedup vs baseline: 1.8319x; 1.8319x over previous
#include <cuda_runtime.h>
#include <math.h>
#include <stdint.h>

#define G    12
#define H    8
#define CQK  32
#define CVAL 32
#define CIN  64
#define COUT 64
#define BATCH 2
#define SEQ  512
#define T_TOK (BATCH*SEQ)   // 1024 tokens
#define DIN  (G*CIN)        // 768
#define DQK  (G*H*CQK)      // 3072
#define GH   (G*H)          // 96

// ---------------- scratch (device globals; no allocation allowed) ----------
__device__ float g_q [T_TOK*DQK];
__device__ float g_k [T_TOK*DQK];
__device__ float g_v [T_TOK*DQK];
__device__ float g_qT[T_TOK*DQK];   // [b][gh][n][32]
__device__ float g_kT[T_TOK*DQK];
__device__ float g_vT[T_TOK*DQK];
__device__ float g_ao[T_TOK*DQK];   // attention out, token-major [t][gh*32+d]

__device__ __forceinline__ uint32_t f2tf32(float x) {
    uint32_t u;
    asm("cvt.rna.tf32.f32 %0, %1;" : "=r"(u) : "f"(x));
    return u;
}

// ---------------- block-circulant GEMM, tf32 tensor cores -------------------
// Y[t][go*CO+o] = sum_{gi,i} X[t][gi*CI+i] * W[(gi-go)%G][o][i]
// BM = 64*MT tokens, BN = 64 outputs, BK = 32.  8 warps = 4(M) x 2(N),
// warp tile (16*MT) x 32 via mma.sync.m16n8k8.tf32.  BK divides CI and BN
// divides CO, so each (k-tile, n-tile) touches exactly one (gi, go) pair.
// Up to 3 independent problems share X via blockIdx.z (fused QKV).
template<int CO, int CI, int MT>
__global__ void __launch_bounds__(256) circ_gemm_tf32(
    const float* __restrict__ X,
    const float* __restrict__ W0, const float* __restrict__ W1,
    const float* __restrict__ W2,
    float* __restrict__ Y0, float* __restrict__ Y1, float* __restrict__ Y2)
{
    constexpr int BM   = 64 * MT;
    constexpr int Ktot = G * CI;
    constexpr int Ntot = G * CO;

    const float* W = (blockIdx.z == 0) ? W0 : (blockIdx.z == 1) ? W1 : W2;
    float*       Y = (blockIdx.z == 0) ? Y0 : (blockIdx.z == 1) ? Y1 : Y2;

    __shared__ uint32_t As[BM][36];   // [token][k], pad 36 -> conflict-free frags
    __shared__ uint32_t Bs[64][36];   // [out][k]

    const int tid = threadIdx.x;
    const int n0 = blockIdx.x * 64;
    const int t0 = blockIdx.y * BM;
    const int go = n0 / CO;
    const int o0 = n0 % CO;

    const int wid    = tid >> 5;
    const int lane   = tid & 31;
    const int warp_m = wid & 3;        // 0..3
    const int warp_n = wid >> 2;       // 0..1
    const int grp    = lane >> 2;      // 0..7
    const int qd     = lane & 3;       // 0..3

    const int lrow = tid >> 3;         // 0..31  (global->smem copy row)
    const int lc4  = (tid & 7) * 4;    // 0,4,...,28

    float acc[MT][4][4];
    #pragma unroll
    for (int mt = 0; mt < MT; mt++)
        #pragma unroll
        for (int nt = 0; nt < 4; nt++)
            #pragma unroll
            for (int i = 0; i < 4; i++) acc[mt][nt][i] = 0.0f;

    for (int kk = 0; kk < Ktot; kk += 32) {
        const int gi = kk / CI;
        const int i0 = kk % CI;
        const int wg = (gi - go + G) % G;

        // X tile: BM rows x 32 k
        #pragma unroll
        for (int rr = 0; rr < BM; rr += 32) {
            const int row = rr + lrow;
            float4 v = *(const float4*)(X + (size_t)(t0 + row) * Ktot + kk + lc4);
            As[row][lc4 + 0] = f2tf32(v.x);
            As[row][lc4 + 1] = f2tf32(v.y);
            As[row][lc4 + 2] = f2tf32(v.z);
            As[row][lc4 + 3] = f2tf32(v.w);
        }
        // W tile: 64 rows x 32 k
        #pragma unroll
        for (int rr = 0; rr < 64; rr += 32) {
            const int row = rr + lrow;
            float4 v = *(const float4*)(W + ((size_t)wg * CO + o0 + row) * CI + i0 + lc4);
            Bs[row][lc4 + 0] = f2tf32(v.x);
            Bs[row][lc4 + 1] = f2tf32(v.y);
            Bs[row][lc4 + 2] = f2tf32(v.z);
            Bs[row][lc4 + 3] = f2tf32(v.w);
        }
        __syncthreads();

        #pragma unroll
        for (int ks = 0; ks < 4; ks++) {
            const int kb = ks * 8;
            uint32_t a[MT][4];
            #pragma unroll
            for (int mt = 0; mt < MT; mt++) {
                const int mr = warp_m * 16 * MT + mt * 16 + grp;
                a[mt][0] = As[mr    ][kb + qd    ];
                a[mt][1] = As[mr + 8][kb + qd    ];
                a[mt][2] = As[mr    ][kb + qd + 4];
                a[mt][3] = As[mr + 8][kb + qd + 4];
            }
            uint32_t b[4][2];
            #pragma unroll
            for (int nt = 0; nt < 4; nt++) {
                const int nc = warp_n * 32 + nt * 8 + grp;
                b[nt][0] = Bs[nc][kb + qd    ];
                b[nt][1] = Bs[nc][kb + qd + 4];
            }
            #pragma unroll
            for (int mt = 0; mt < MT; mt++)
                #pragma unroll
                for (int nt = 0; nt < 4; nt++) {
                    asm volatile(
                        "mma.sync.aligned.m16n8k8.row.col.f32.tf32.tf32.f32 "
                        "{%0,%1,%2,%3}, {%4,%5,%6,%7}, {%8,%9}, {%0,%1,%2,%3};"
                        : "+f"(acc[mt][nt][0]), "+f"(acc[mt][nt][1]),
                          "+f"(acc[mt][nt][2]), "+f"(acc[mt][nt][3])
                        : "r"(a[mt][0]), "r"(a[mt][1]), "r"(a[mt][2]), "r"(a[mt][3]),
                          "r"(b[nt][0]), "r"(b[nt][1]));
                }
        }
        __syncthreads();
    }

    // epilogue: c0,c1 at (grp, 2*qd[+1]); c2,c3 at (grp+8, 2*qd[+1])
    #pragma unroll
    for (int mt = 0; mt < MT; mt++) {
        const int trow = t0 + warp_m * 16 * MT + mt * 16 + grp;
        #pragma unroll
        for (int nt = 0; nt < 4; nt++) {
            const int ncol = n0 + warp_n * 32 + nt * 8 + 2 * qd;
            *(float2*)&Y[(size_t)trow * Ntot + ncol] =
                make_float2(acc[mt][nt][0], acc[mt][nt][1]);
            *(float2*)&Y[(size_t)(trow + 8) * Ntot + ncol] =
                make_float2(acc[mt][nt][2], acc[mt][nt][3]);
        }
    }
}

// ---------------- rms_norm + sequence rope + platonic rope + transpose ----
__global__ void __launch_bounds__(256) rope_kernel(
    const float* __restrict__ coords, const int* __restrict__ seq_idx,
    const float* __restrict__ qnw, const float* __restrict__ knw,
    const float* __restrict__ pfreqs)
{
    const int t = blockIdx.x;
    const int b = t / SEQ, n = t % SEQ;
    const float cx = coords[t * 3 + 0];
    const float cy = coords[t * 3 + 1];
    const float cz = coords[t * 3 + 2];
    const float pos = (float)seq_idx[t];
    const float EPS = 1.1920929e-07f;
    const float LOG1E4_OV16 = 9.210340371976184f / 16.0f;

    for (int base = 0; base < GH * 16; base += 256) {
        const int p  = base + threadIdx.x;
        const int gh = p >> 4;
        const int f  = p & 15;
        const int g  = gh >> 3;
        const int h  = gh & 7;

        const int off = t * DQK + gh * 32 + 2 * f;
        float q1 = g_q[off], q2 = g_q[off + 1];
        float k1 = g_k[off], k2 = g_k[off + 1];

        float sq = q1 * q1 + q2 * q2;
        float sk = k1 * k1 + k2 * k2;
        #pragma unroll
        for (int o2 = 8; o2 > 0; o2 >>= 1) {
            sq += __shfl_xor_sync(0xffffffffu, sq, o2, 16);
            sk += __shfl_xor_sync(0xffffffffu, sk, o2, 16);
        }
        const float rq = rsqrtf(sq * (1.0f / 32.0f) + EPS);
        const float rk = rsqrtf(sk * (1.0f / 32.0f) + EPS);
        q1 *= rq * qnw[2 * f];  q2 *= rq * qnw[2 * f + 1];
        k1 *= rk * knw[2 * f];  k2 *= rk * knw[2 * f + 1];

        const float invf = expf(-(float)f * LOG1E4_OV16);
        const float ang  = pos * invf;

        const float th = 6.283185307179586f * (float)g * (1.0f / 12.0f);
        float sg, cg;  sincosf(th, &sg, &cg);
        const float c0 =  cx * cg + cy * sg;
        const float c1 = -cx * sg + cy * cg;
        const float* fr = pfreqs + (h * 16 + f) * 3;
        const float ph  = c0 * fr[0] + c1 * fr[1] + cz * fr[2];

        float s, c;  sincosf(ang + ph, &s, &c);
        const float qo1 = q1 * c - q2 * s, qo2 = q1 * s + q2 * c;
        const float ko1 = k1 * c - k2 * s, ko2 = k1 * s + k2 * c;

        const size_t dst = (((size_t)b * GH + gh) * SEQ + n) * 32 + 2 * f;
        g_qT[dst] = qo1;  g_qT[dst + 1] = qo2;
        g_kT[dst] = ko1;  g_kT[dst + 1] = ko2;
    }

    for (int i = threadIdx.x; i < DQK; i += 256) {
        const int gh = i >> 5, d = i & 31;
        g_vT[(((size_t)b * GH + gh) * SEQ + n) * 32 + d] = g_v[(size_t)t * DQK + i];
    }
}

// ---------------- attention ------------------------------------------------
__global__ void __launch_bounds__(256) attn_kernel()
{
    extern __shared__ float sh[];
    float* Ks = sh;              // 512*32
    float* Vs = sh + SEQ * 32;   // 512*32

    const int qc = blockIdx.x;   // 0..1
    const int gh = blockIdx.y;   // 0..95
    const int b  = blockIdx.z;   // 0..1

    const size_t base = (((size_t)b * GH + gh) * SEQ) * 32;
    {
        const float4* kg = (const float4*)(g_kT + base);
        const float4* vg = (const float4*)(g_vT + base);
        float4* ks4 = (float4*)Ks;
        float4* vs4 = (float4*)Vs;
        for (int i = threadIdx.x; i < SEQ * 8; i += 256) {
            ks4[i] = kg[i];
            vs4[i] = vg[i];
        }
    }
    __syncthreads();

    const int n = qc * 256 + threadIdx.x;
    float4 q[8];
    {
        const float4* qg = (const float4*)(g_qT + base + (size_t)n * 32);
        #pragma unroll
        for (int i = 0; i < 8; i++) q[i] = qg[i];
    }
    const float scale = 0.17677669529663687f;

    float m = -1e30f;
    for (int j = 0; j < SEQ; j++) {
        const float4* kp = (const float4*)(Ks + j * 32);
        float s = 0.0f;
        #pragma unroll
        for (int i = 0; i < 8; i++) {
            float4 kv = kp[i];
            s += q[i].x * kv.x + q[i].y * kv.y + q[i].z * kv.z + q[i].w * kv.w;
        }
        m = fmaxf(m, s * scale);
    }

    float l = 0.0f;
    float4 acc[8];
    #pragma unroll
    for (int i = 0; i < 8; i++) acc[i] = make_float4(0.f, 0.f, 0.f, 0.f);
    for (int j = 0; j < SEQ; j++) {
        const float4* kp = (const float4*)(Ks + j * 32);
        float s = 0.0f;
        #pragma unroll
        for (int i = 0; i < 8; i++) {
            float4 kv = kp[i];
            s += q[i].x * kv.x + q[i].y * kv.y + q[i].z * kv.z + q[i].w * kv.w;
        }
        const float p = expf(s * scale - m);
        l += p;
        const float4* vp = (const float4*)(Vs + j * 32);
        #pragma unroll
        for (int i = 0; i < 8; i++) {
            float4 vv = vp[i];
            acc[i].x += p * vv.x;  acc[i].y += p * vv.y;
            acc[i].z += p * vv.z;  acc[i].w += p * vv.w;
        }
    }

    const float inv = 1.0f / l;
    float4* og = (float4*)(g_ao + ((size_t)(b * SEQ + n)) * DQK + gh * 32);
    #pragma unroll
    for (int i = 0; i < 8; i++) {
        float4 o = acc[i];
        o.x *= inv;  o.y *= inv;  o.z *= inv;  o.w *= inv;
        og[i] = o;
    }
}

// ---------------- launch ---------------------------------------------------
extern "C" void kernel_launch(void* const* d_in, const int* in_sizes, int n_in,
                              void* d_out, int out_size)
{
    const float* feat   = (const float*)d_in[0];
    const float* coords = (const float*)d_in[1];
    const float* Wq     = (const float*)d_in[2];
    const float* Wk     = (const float*)d_in[3];
    const float* Wv     = (const float*)d_in[4];
    const float* Wo     = (const float*)d_in[5];
    const float* qnw    = (const float*)d_in[6];
    const float* knw    = (const float*)d_in[7];
    const float* pfrq   = (const float*)d_in[8];
    const int*   sidx   = (const int*)d_in[9];
    float* out = (float*)d_out;

    void *pq, *pk, *pv, *pao;
    cudaGetSymbolAddress(&pq,  g_q);
    cudaGetSymbolAddress(&pk,  g_k);
    cudaGetSymbolAddress(&pv,  g_v);
    cudaGetSymbolAddress(&pao, g_ao);

    // fused QKV projections: z selects {Wq,Wk,Wv} -> {g_q,g_k,g_v}
    circ_gemm_tf32<H * CQK, CIN, 2><<<dim3(DQK / 64, T_TOK / 128, 3), 256>>>(
        feat, Wq, Wk, Wv, (float*)pq, (float*)pk, (float*)pv);

    // norm + ropes + transpose
    rope_kernel<<<T_TOK, 256>>>(coords, sidx, qnw, knw, pfrq);

    // attention (128 KB dynamic smem: opt-in required)
    cudaFuncSetAttribute(attn_kernel,
                         cudaFuncAttributeMaxDynamicSharedMemorySize, 131072);
    attn_kernel<<<dim3(2, GH, BATCH), 256, 131072>>>();

    // output projection: M=1024 x N=768 (K=3072), BM=64 for 192 blocks
    circ_gemm_tf32<COUT, H * CVAL, 1><<<dim3(G * COUT / 64, T_TOK / 64, 1), 256>>>(
        (const float*)pao, Wo, Wo, Wo, out, out, out);
}

// round 5
// speedup vs baseline: 3.1969x; 1.7451x over previous
#include <cuda_runtime.h>
#include <math.h>
#include <stdint.h>

#define G    12
#define H    8
#define CQK  32
#define CVAL 32
#define CIN  64
#define COUT 64
#define BATCH 2
#define SEQ  512
#define T_TOK (BATCH*SEQ)   // 1024 tokens
#define DIN  (G*CIN)        // 768
#define DQK  (G*H*CQK)      // 3072
#define GH   (G*H)          // 96

// ---------------- scratch (device globals; no allocation allowed) ----------
__device__ float g_q  [T_TOK*DQK];
__device__ float g_k  [T_TOK*DQK];
__device__ float g_v  [T_TOK*DQK];
__device__ float g_qT [T_TOK*DQK];   // [b][gh][n][32]
__device__ float g_kT [T_TOK*DQK];   // [b][gh][n][32]
__device__ float g_vTd[T_TOK*DQK];   // [b][gh][d][n]   (d-major for attn V frags)
__device__ float g_ao [T_TOK*DQK];   // attention out, token-major [t][gh*32+d]

__device__ __forceinline__ uint32_t f2tf32(float x) {
    uint32_t u;
    asm("cvt.rna.tf32.f32 %0, %1;" : "=r"(u) : "f"(x));
    return u;
}

__device__ __forceinline__ void mma_tf32(float* c, const uint32_t* a,
                                         uint32_t b0, uint32_t b1) {
    asm volatile(
        "mma.sync.aligned.m16n8k8.row.col.f32.tf32.tf32.f32 "
        "{%0,%1,%2,%3}, {%4,%5,%6,%7}, {%8,%9}, {%0,%1,%2,%3};"
        : "+f"(c[0]), "+f"(c[1]), "+f"(c[2]), "+f"(c[3])
        : "r"(a[0]), "r"(a[1]), "r"(a[2]), "r"(a[3]), "r"(b0), "r"(b1));
}

// ---------------- block-circulant GEMM, tf32 tensor cores -------------------
template<int CO, int CI, int MT>
__global__ void __launch_bounds__(256) circ_gemm_tf32(
    const float* __restrict__ X,
    const float* __restrict__ W0, const float* __restrict__ W1,
    const float* __restrict__ W2,
    float* __restrict__ Y0, float* __restrict__ Y1, float* __restrict__ Y2)
{
    constexpr int BM   = 64 * MT;
    constexpr int Ktot = G * CI;
    constexpr int Ntot = G * CO;

    const float* W = (blockIdx.z == 0) ? W0 : (blockIdx.z == 1) ? W1 : W2;
    float*       Y = (blockIdx.z == 0) ? Y0 : (blockIdx.z == 1) ? Y1 : Y2;

    __shared__ uint32_t As[BM][36];
    __shared__ uint32_t Bs[64][36];

    const int tid = threadIdx.x;
    const int n0 = blockIdx.x * 64;
    const int t0 = blockIdx.y * BM;
    const int go = n0 / CO;
    const int o0 = n0 % CO;

    const int wid    = tid >> 5;
    const int lane   = tid & 31;
    const int warp_m = wid & 3;
    const int warp_n = wid >> 2;
    const int grp    = lane >> 2;
    const int qd     = lane & 3;

    const int lrow = tid >> 3;
    const int lc4  = (tid & 7) * 4;

    float acc[MT][4][4];
    #pragma unroll
    for (int mt = 0; mt < MT; mt++)
        #pragma unroll
        for (int nt = 0; nt < 4; nt++)
            #pragma unroll
            for (int i = 0; i < 4; i++) acc[mt][nt][i] = 0.0f;

    for (int kk = 0; kk < Ktot; kk += 32) {
        const int gi = kk / CI;
        const int i0 = kk % CI;
        const int wg = (gi - go + G) % G;

        #pragma unroll
        for (int rr = 0; rr < BM; rr += 32) {
            const int row = rr + lrow;
            float4 v = *(const float4*)(X + (size_t)(t0 + row) * Ktot + kk + lc4);
            As[row][lc4 + 0] = f2tf32(v.x);
            As[row][lc4 + 1] = f2tf32(v.y);
            As[row][lc4 + 2] = f2tf32(v.z);
            As[row][lc4 + 3] = f2tf32(v.w);
        }
        #pragma unroll
        for (int rr = 0; rr < 64; rr += 32) {
            const int row = rr + lrow;
            float4 v = *(const float4*)(W + ((size_t)wg * CO + o0 + row) * CI + i0 + lc4);
            Bs[row][lc4 + 0] = f2tf32(v.x);
            Bs[row][lc4 + 1] = f2tf32(v.y);
            Bs[row][lc4 + 2] = f2tf32(v.z);
            Bs[row][lc4 + 3] = f2tf32(v.w);
        }
        __syncthreads();

        #pragma unroll
        for (int ks = 0; ks < 4; ks++) {
            const int kb = ks * 8;
            uint32_t a[MT][4];
            #pragma unroll
            for (int mt = 0; mt < MT; mt++) {
                const int mr = warp_m * 16 * MT + mt * 16 + grp;
                a[mt][0] = As[mr    ][kb + qd    ];
                a[mt][1] = As[mr + 8][kb + qd    ];
                a[mt][2] = As[mr    ][kb + qd + 4];
                a[mt][3] = As[mr + 8][kb + qd + 4];
            }
            uint32_t b[4][2];
            #pragma unroll
            for (int nt = 0; nt < 4; nt++) {
                const int nc = warp_n * 32 + nt * 8 + grp;
                b[nt][0] = Bs[nc][kb + qd    ];
                b[nt][1] = Bs[nc][kb + qd + 4];
            }
            #pragma unroll
            for (int mt = 0; mt < MT; mt++)
                #pragma unroll
                for (int nt = 0; nt < 4; nt++)
                    mma_tf32(acc[mt][nt], a[mt], b[nt][0], b[nt][1]);
        }
        __syncthreads();
    }

    #pragma unroll
    for (int mt = 0; mt < MT; mt++) {
        const int trow = t0 + warp_m * 16 * MT + mt * 16 + grp;
        #pragma unroll
        for (int nt = 0; nt < 4; nt++) {
            const int ncol = n0 + warp_n * 32 + nt * 8 + 2 * qd;
            *(float2*)&Y[(size_t)trow * Ntot + ncol] =
                make_float2(acc[mt][nt][0], acc[mt][nt][1]);
            *(float2*)&Y[(size_t)(trow + 8) * Ntot + ncol] =
                make_float2(acc[mt][nt][2], acc[mt][nt][3]);
        }
    }
}

// ---------------- rms_norm + sequence rope + platonic rope + transpose ----
__global__ void __launch_bounds__(256) rope_kernel(
    const float* __restrict__ coords, const int* __restrict__ seq_idx,
    const float* __restrict__ qnw, const float* __restrict__ knw,
    const float* __restrict__ pfreqs)
{
    const int t = blockIdx.x;
    const int b = t / SEQ, n = t % SEQ;
    const float cx = coords[t * 3 + 0];
    const float cy = coords[t * 3 + 1];
    const float cz = coords[t * 3 + 2];
    const float pos = (float)seq_idx[t];
    const float EPS = 1.1920929e-07f;
    const float LOG1E4_OV16 = 9.210340371976184f / 16.0f;

    for (int base = 0; base < GH * 16; base += 256) {
        const int p  = base + threadIdx.x;
        const int gh = p >> 4;
        const int f  = p & 15;
        const int g  = gh >> 3;
        const int h  = gh & 7;

        const int off = t * DQK + gh * 32 + 2 * f;
        float q1 = g_q[off], q2 = g_q[off + 1];
        float k1 = g_k[off], k2 = g_k[off + 1];

        float sq = q1 * q1 + q2 * q2;
        float sk = k1 * k1 + k2 * k2;
        #pragma unroll
        for (int o2 = 8; o2 > 0; o2 >>= 1) {
            sq += __shfl_xor_sync(0xffffffffu, sq, o2, 16);
            sk += __shfl_xor_sync(0xffffffffu, sk, o2, 16);
        }
        const float rq = rsqrtf(sq * (1.0f / 32.0f) + EPS);
        const float rk = rsqrtf(sk * (1.0f / 32.0f) + EPS);
        q1 *= rq * qnw[2 * f];  q2 *= rq * qnw[2 * f + 1];
        k1 *= rk * knw[2 * f];  k2 *= rk * knw[2 * f + 1];

        const float invf = expf(-(float)f * LOG1E4_OV16);
        const float ang  = pos * invf;

        const float th = 6.283185307179586f * (float)g * (1.0f / 12.0f);
        float sg, cg;  sincosf(th, &sg, &cg);
        const float c0 =  cx * cg + cy * sg;
        const float c1 = -cx * sg + cy * cg;
        const float* fr = pfreqs + (h * 16 + f) * 3;
        const float ph  = c0 * fr[0] + c1 * fr[1] + cz * fr[2];

        float s, c;  sincosf(ang + ph, &s, &c);
        const float qo1 = q1 * c - q2 * s, qo2 = q1 * s + q2 * c;
        const float ko1 = k1 * c - k2 * s, ko2 = k1 * s + k2 * c;

        const size_t dst = (((size_t)b * GH + gh) * SEQ + n) * 32 + 2 * f;
        g_qT[dst] = qo1;  g_qT[dst + 1] = qo2;
        g_kT[dst] = ko1;  g_kT[dst + 1] = ko2;
    }

    // V transpose: token-major -> [b][gh][d][n] (d-major for attn V B-frags)
    for (int i = threadIdx.x; i < DQK; i += 256) {
        const int gh = i >> 5, d = i & 31;
        g_vTd[(((size_t)b * GH + gh) * 32 + d) * SEQ + n] = g_v[(size_t)t * DQK + i];
    }
}

// ---------------- attention: flash-style tf32 MMA ---------------------------
// Block = (b, head, half of queries). 8 warps x 32 queries. K split hi/lo
// (3xTF32 for QK^T, full fp32-class logits); V single tf32 for PV.
// smem: Khi[512][36] + Klo[512][36] + Vt[32][516]  = 213504 B.
#define KPAD 36
#define VPAD 516
#define ATTN_SMEM ((2*512*KPAD + 32*VPAD) * 4)

__global__ void __launch_bounds__(256) attn_mma_kernel()
{
    extern __shared__ uint32_t sh_u[];
    uint32_t* Khi = sh_u;
    uint32_t* Klo = sh_u + 512 * KPAD;
    uint32_t* Vt  = sh_u + 2 * 512 * KPAD;

    const int qc = blockIdx.x;   // 0..1
    const int gh = blockIdx.y;   // 0..95
    const int b  = blockIdx.z;   // 0..1
    const int tid  = threadIdx.x;
    const int wid  = tid >> 5;
    const int lane = tid & 31;
    const int grp  = lane >> 2;  // 0..7
    const int qd   = lane & 3;   // 0..3

    const size_t base  = (((size_t)b * GH + gh) * SEQ) * 32;
    const size_t vbase = (((size_t)b * GH + gh) * 32) * SEQ;

    // ---- prologue: K -> hi/lo tf32, V -> tf32 (already d-major) ----
    {
        const int key0 = tid >> 3;
        const int c4   = (tid & 7) * 4;
        for (int key = key0; key < SEQ; key += 32) {
            float4 v = *(const float4*)(g_kT + base + (size_t)key * 32 + c4);
            uint32_t h0 = f2tf32(v.x), h1 = f2tf32(v.y);
            uint32_t h2 = f2tf32(v.z), h3 = f2tf32(v.w);
            uint32_t l0 = f2tf32(v.x - __uint_as_float(h0));
            uint32_t l1 = f2tf32(v.y - __uint_as_float(h1));
            uint32_t l2 = f2tf32(v.z - __uint_as_float(h2));
            uint32_t l3 = f2tf32(v.w - __uint_as_float(h3));
            *(uint4*)&Khi[key * KPAD + c4] = make_uint4(h0, h1, h2, h3);
            *(uint4*)&Klo[key * KPAD + c4] = make_uint4(l0, l1, l2, l3);
        }
        const int d0 = tid >> 3;   // 0..31
        for (int kk = (tid & 7) * 4; kk < SEQ; kk += 32) {
            float4 v = *(const float4*)(g_vTd + vbase + (size_t)d0 * SEQ + kk);
            *(uint4*)&Vt[d0 * VPAD + kk] =
                make_uint4(f2tf32(v.x), f2tf32(v.y), f2tf32(v.z), f2tf32(v.w));
        }
    }
    __syncthreads();

    // ---- per-warp Q fragments (scaled, hi/lo split) ----
    const int qrow0 = qc * 256 + wid * 32;
    const float scale = 0.17677669529663687f;   // 1/sqrt(32)
    uint32_t qhi[2][4][4], qlo[2][4][4];
    #pragma unroll
    for (int mt = 0; mt < 2; mt++)
        #pragma unroll
        for (int ks = 0; ks < 4; ks++)
            #pragma unroll
            for (int e = 0; e < 4; e++) {
                const int row = mt * 16 + grp + (e & 1) * 8;
                const int col = ks * 8 + qd + (e >> 1) * 4;
                float x = g_qT[base + (size_t)(qrow0 + row) * 32 + col] * scale;
                uint32_t h = f2tf32(x);
                qhi[mt][ks][e] = h;
                qlo[mt][ks][e] = f2tf32(x - __uint_as_float(h));
            }

    float mrow[2][2], lrow[2][2];
    float o[2][4][4];
    #pragma unroll
    for (int mt = 0; mt < 2; mt++)
        #pragma unroll
        for (int h = 0; h < 2; h++) { mrow[mt][h] = -1e30f; lrow[mt][h] = 0.0f; }
    #pragma unroll
    for (int mt = 0; mt < 2; mt++)
        #pragma unroll
        for (int nt = 0; nt < 4; nt++)
            #pragma unroll
            for (int c = 0; c < 4; c++) o[mt][nt][c] = 0.0f;

    float s[2][8][4];

    for (int kt = 0; kt < 8; kt++) {        // 8 key tiles of 64
        // ---- QK^T (3xTF32) ----
        #pragma unroll
        for (int mt = 0; mt < 2; mt++)
            #pragma unroll
            for (int nt = 0; nt < 8; nt++)
                #pragma unroll
                for (int c = 0; c < 4; c++) s[mt][nt][c] = 0.0f;

        #pragma unroll
        for (int ks = 0; ks < 4; ks++) {
            #pragma unroll
            for (int nt = 0; nt < 8; nt++) {
                const int key = kt * 64 + nt * 8 + grp;
                const int kc  = ks * 8 + qd;
                uint32_t bh0 = Khi[key * KPAD + kc];
                uint32_t bh1 = Khi[key * KPAD + kc + 4];
                uint32_t bl0 = Klo[key * KPAD + kc];
                uint32_t bl1 = Klo[key * KPAD + kc + 4];
                #pragma unroll
                for (int mt = 0; mt < 2; mt++) {
                    mma_tf32(s[mt][nt], qhi[mt][ks], bh0, bh1);
                    mma_tf32(s[mt][nt], qhi[mt][ks], bl0, bl1);
                    mma_tf32(s[mt][nt], qlo[mt][ks], bh0, bh1);
                }
            }
        }

        // ---- online softmax (C layout) ----
        float esc[2][2];
        #pragma unroll
        for (int mt = 0; mt < 2; mt++)
            #pragma unroll
            for (int h = 0; h < 2; h++) {
                float mx = -1e30f;
                #pragma unroll
                for (int nt = 0; nt < 8; nt++)
                    mx = fmaxf(mx, fmaxf(s[mt][nt][2 * h], s[mt][nt][2 * h + 1]));
                mx = fmaxf(mx, __shfl_xor_sync(0xffffffffu, mx, 1));
                mx = fmaxf(mx, __shfl_xor_sync(0xffffffffu, mx, 2));
                const float mnew = fmaxf(mrow[mt][h], mx);
                esc[mt][h] = expf(mrow[mt][h] - mnew);
                mrow[mt][h] = mnew;
            }
        #pragma unroll
        for (int mt = 0; mt < 2; mt++)
            #pragma unroll
            for (int nt = 0; nt < 8; nt++)
                #pragma unroll
                for (int c = 0; c < 4; c++)
                    s[mt][nt][c] = expf(s[mt][nt][c] - mrow[mt][c >> 1]);
        #pragma unroll
        for (int mt = 0; mt < 2; mt++)
            #pragma unroll
            for (int h = 0; h < 2; h++) {
                float ps = 0.0f;
                #pragma unroll
                for (int nt = 0; nt < 8; nt++)
                    ps += s[mt][nt][2 * h] + s[mt][nt][2 * h + 1];
                ps += __shfl_xor_sync(0xffffffffu, ps, 1);
                ps += __shfl_xor_sync(0xffffffffu, ps, 2);
                lrow[mt][h] = lrow[mt][h] * esc[mt][h] + ps;
            }
        #pragma unroll
        for (int mt = 0; mt < 2; mt++)
            #pragma unroll
            for (int nt = 0; nt < 4; nt++)
                #pragma unroll
                for (int c = 0; c < 4; c++)
                    o[mt][nt][c] *= esc[mt][c >> 1];

        // ---- P·V ----
        const int s1 = grp * 4 + (qd >> 1);
        const int s2 = s1 + 2;
        const bool odd = (qd & 1);
        #pragma unroll
        for (int ks = 0; ks < 8; ks++) {
            uint32_t a[2][4];
            #pragma unroll
            for (int mt = 0; mt < 2; mt++) {
                uint32_t u0 = f2tf32(s[mt][ks][0]);
                uint32_t u1 = f2tf32(s[mt][ks][1]);
                uint32_t u2 = f2tf32(s[mt][ks][2]);
                uint32_t u3 = f2tf32(s[mt][ks][3]);
                uint32_t v00 = __shfl_sync(0xffffffffu, u0, s1);
                uint32_t v01 = __shfl_sync(0xffffffffu, u1, s1);
                uint32_t v20 = __shfl_sync(0xffffffffu, u2, s1);
                uint32_t v21 = __shfl_sync(0xffffffffu, u3, s1);
                uint32_t w00 = __shfl_sync(0xffffffffu, u0, s2);
                uint32_t w01 = __shfl_sync(0xffffffffu, u1, s2);
                uint32_t w20 = __shfl_sync(0xffffffffu, u2, s2);
                uint32_t w21 = __shfl_sync(0xffffffffu, u3, s2);
                a[mt][0] = odd ? v01 : v00;
                a[mt][1] = odd ? v21 : v20;
                a[mt][2] = odd ? w01 : w00;
                a[mt][3] = odd ? w21 : w20;
            }
            #pragma unroll
            for (int nt = 0; nt < 4; nt++) {
                const int col = kt * 64 + ks * 8 + qd;
                uint32_t b0 = Vt[(nt * 8 + grp) * VPAD + col];
                uint32_t b1 = Vt[(nt * 8 + grp) * VPAD + col + 4];
                #pragma unroll
                for (int mt = 0; mt < 2; mt++)
                    mma_tf32(o[mt][nt], a[mt], b0, b1);
            }
        }
    }

    // ---- epilogue ----
    #pragma unroll
    for (int mt = 0; mt < 2; mt++) {
        const float inv0 = 1.0f / lrow[mt][0];
        const float inv1 = 1.0f / lrow[mt][1];
        const int n0 = qrow0 + mt * 16 + grp;
        #pragma unroll
        for (int nt = 0; nt < 4; nt++) {
            const int gcol = gh * 32 + nt * 8 + 2 * qd;
            *(float2*)&g_ao[((size_t)(b * SEQ + n0)) * DQK + gcol] =
                make_float2(o[mt][nt][0] * inv0, o[mt][nt][1] * inv0);
            *(float2*)&g_ao[((size_t)(b * SEQ + n0 + 8)) * DQK + gcol] =
                make_float2(o[mt][nt][2] * inv1, o[mt][nt][3] * inv1);
        }
    }
}

// ---------------- launch ---------------------------------------------------
extern "C" void kernel_launch(void* const* d_in, const int* in_sizes, int n_in,
                              void* d_out, int out_size)
{
    const float* feat   = (const float*)d_in[0];
    const float* coords = (const float*)d_in[1];
    const float* Wq     = (const float*)d_in[2];
    const float* Wk     = (const float*)d_in[3];
    const float* Wv     = (const float*)d_in[4];
    const float* Wo     = (const float*)d_in[5];
    const float* qnw    = (const float*)d_in[6];
    const float* knw    = (const float*)d_in[7];
    const float* pfrq   = (const float*)d_in[8];
    const int*   sidx   = (const int*)d_in[9];
    float* out = (float*)d_out;

    void *pq, *pk, *pv, *pao;
    cudaGetSymbolAddress(&pq,  g_q);
    cudaGetSymbolAddress(&pk,  g_k);
    cudaGetSymbolAddress(&pv,  g_v);
    cudaGetSymbolAddress(&pao, g_ao);

    // fused QKV projections
    circ_gemm_tf32<H * CQK, CIN, 2><<<dim3(DQK / 64, T_TOK / 128, 3), 256>>>(
        feat, Wq, Wk, Wv, (float*)pq, (float*)pk, (float*)pv);

    // norm + ropes + transpose
    rope_kernel<<<T_TOK, 256>>>(coords, sidx, qnw, knw, pfrq);

    // attention (213.5 KB dynamic smem)
    cudaFuncSetAttribute(attn_mma_kernel,
                         cudaFuncAttributeMaxDynamicSharedMemorySize, ATTN_SMEM);
    attn_mma_kernel<<<dim3(2, GH, BATCH), 256, ATTN_SMEM>>>();

    // output projection
    circ_gemm_tf32<COUT, H * CVAL, 1><<<dim3(G * COUT / 64, T_TOK / 64, 1), 256>>>(
        (const float*)pao, Wo, Wo, Wo, out, out, out);
}

// round 6
// speedup vs baseline: 3.3319x; 1.0422x over previous
#include <cuda_runtime.h>
#include <math.h>
#include <stdint.h>

#define G    12
#define H    8
#define CQK  32
#define CVAL 32
#define CIN  64
#define COUT 64
#define BATCH 2
#define SEQ  512
#define T_TOK (BATCH*SEQ)   // 1024 tokens
#define DIN  (G*CIN)        // 768
#define DQK  (G*H*CQK)      // 3072
#define GH   (G*H)          // 96
#define DOUT (G*COUT)       // 768

// ---------------- scratch (device globals; no allocation allowed) ----------
__device__ float g_q  [T_TOK*DQK];
__device__ float g_k  [T_TOK*DQK];
__device__ float g_v  [T_TOK*DQK];
__device__ float g_qT [T_TOK*DQK];   // [b][gh][n][32]
__device__ float g_kT [T_TOK*DQK];   // [b][gh][n][32]
__device__ float g_vTd[T_TOK*DQK];   // [b][gh][d][n]
__device__ float g_ao [T_TOK*DQK];   // attention out, token-major
__device__ float g_part[4*T_TOK*DOUT]; // Wo split-K partials

__device__ __forceinline__ uint32_t f2tf32(float x) {
    uint32_t u;
    asm("cvt.rna.tf32.f32 %0, %1;" : "=r"(u) : "f"(x));
    return u;
}

__device__ __forceinline__ void mma_tf32(float* c, const uint32_t* a,
                                         uint32_t b0, uint32_t b1) {
    asm volatile(
        "mma.sync.aligned.m16n8k8.row.col.f32.tf32.tf32.f32 "
        "{%0,%1,%2,%3}, {%4,%5,%6,%7}, {%8,%9}, {%0,%1,%2,%3};"
        : "+f"(c[0]), "+f"(c[1]), "+f"(c[2]), "+f"(c[3])
        : "r"(a[0]), "r"(a[1]), "r"(a[2]), "r"(a[3]), "r"(b0), "r"(b1));
}

__device__ __forceinline__ void cpa16(float* smem, const float* gmem) {
    uint32_t s = (uint32_t)__cvta_generic_to_shared(smem);
    asm volatile("cp.async.cg.shared.global [%0], [%1], 16;" :: "r"(s), "l"(gmem));
}

// ---------------- block-circulant GEMM v2: cp.async double-buffered tf32 ----
// Y[t][go*CO+o] = sum_{gi,i} X[t][gi*CI+i] * W[(gi-go)%G][o][i]
// BM=128 tokens x BN=64 outputs x BK=64.  8 warps = 4(M) x 2(N), warp tile
// 32x32 (MT=2).  KSPLIT>1 writes partials (Y + ksl*T_TOK*Ntot).
// BK=64 divides CI in both uses -> each k-tile maps to one (gi,go) pair.
#define GPAD 68
template<int CO, int CI, int KSPLIT>
__global__ void __launch_bounds__(256) circ_gemm2(
    const float* __restrict__ X,
    const float* __restrict__ W0, const float* __restrict__ W1,
    const float* __restrict__ W2,
    float* __restrict__ Y0, float* __restrict__ Y1, float* __restrict__ Y2)
{
    constexpr int BM   = 128;
    constexpr int BK   = 64;
    constexpr int Ktot = G * CI;
    constexpr int Ntot = G * CO;
    constexpr int Kper = Ktot / KSPLIT;
    constexpr int NIT  = Kper / BK;

    extern __shared__ float sm[];
    float* As = sm;                 // [2][BM][GPAD]
    float* Bs = sm + 2 * BM * GPAD; // [2][64][GPAD]

    const int z    = blockIdx.z;
    const int prob = (KSPLIT == 1) ? z : 0;
    const int ksl  = (KSPLIT == 1) ? 0 : z;
    const float* W = (prob == 0) ? W0 : (prob == 1) ? W1 : W2;
    float* Y = ((prob == 0) ? Y0 : (prob == 1) ? Y1 : Y2)
               + (size_t)ksl * T_TOK * Ntot;

    const int tid = threadIdx.x;
    const int n0 = blockIdx.x * 64;
    const int t0 = blockIdx.y * BM;
    const int go = n0 / CO;
    const int o0 = n0 % CO;

    const int wid    = tid >> 5;
    const int lane   = tid & 31;
    const int warp_m = wid & 3;
    const int warp_n = wid >> 2;
    const int grp    = lane >> 2;
    const int qd     = lane & 3;

    const int kbeg = ksl * Kper;

    // tile loader: As 128x64 (2048 16B-chunks), Bs 64x64 (1024 chunks)
    auto load_tile = [&](int buf, int kk) {
        const int gi = kk / CI;
        const int i0 = kk % CI;
        const int wg = (gi - go + G) % G;
        const float* Xb = X + (size_t)t0 * Ktot + kk;
        const float* Wb = W + ((size_t)wg * CO + o0) * CI + i0;
        float* Ab = As + buf * BM * GPAD;
        float* Bb = Bs + buf * 64 * GPAD;
        #pragma unroll
        for (int i = 0; i < 8; i++) {
            const int ch  = tid + i * 256;
            const int row = ch >> 4;
            const int c4  = (ch & 15) << 2;
            cpa16(Ab + row * GPAD + c4, Xb + (size_t)row * Ktot + c4);
        }
        #pragma unroll
        for (int i = 0; i < 4; i++) {
            const int ch  = tid + i * 256;
            const int row = ch >> 4;
            const int c4  = (ch & 15) << 2;
            cpa16(Bb + row * GPAD + c4, Wb + (size_t)row * CI + c4);
        }
        asm volatile("cp.async.commit_group;");
    };

    float acc[2][4][4];
    #pragma unroll
    for (int mt = 0; mt < 2; mt++)
        #pragma unroll
        for (int nt = 0; nt < 4; nt++)
            #pragma unroll
            for (int i = 0; i < 4; i++) acc[mt][nt][i] = 0.0f;

    load_tile(0, kbeg);

    for (int it = 0; it < NIT; it++) {
        if (it + 1 < NIT) {
            load_tile((it + 1) & 1, kbeg + (it + 1) * BK);
            asm volatile("cp.async.wait_group 1;");
        } else {
            asm volatile("cp.async.wait_group 0;");
        }
        __syncthreads();

        const float* Ab = As + (it & 1) * BM * GPAD;
        const float* Bb = Bs + (it & 1) * 64 * GPAD;

        #pragma unroll
        for (int ks = 0; ks < 8; ks++) {
            const int kb = ks * 8;
            uint32_t a[2][4];
            #pragma unroll
            for (int mt = 0; mt < 2; mt++) {
                const int mr = warp_m * 32 + mt * 16 + grp;
                a[mt][0] = f2tf32(Ab[(mr    ) * GPAD + kb + qd    ]);
                a[mt][1] = f2tf32(Ab[(mr + 8) * GPAD + kb + qd    ]);
                a[mt][2] = f2tf32(Ab[(mr    ) * GPAD + kb + qd + 4]);
                a[mt][3] = f2tf32(Ab[(mr + 8) * GPAD + kb + qd + 4]);
            }
            uint32_t b[4][2];
            #pragma unroll
            for (int nt = 0; nt < 4; nt++) {
                const int nc = warp_n * 32 + nt * 8 + grp;
                b[nt][0] = f2tf32(Bb[nc * GPAD + kb + qd    ]);
                b[nt][1] = f2tf32(Bb[nc * GPAD + kb + qd + 4]);
            }
            #pragma unroll
            for (int mt = 0; mt < 2; mt++)
                #pragma unroll
                for (int nt = 0; nt < 4; nt++)
                    mma_tf32(acc[mt][nt], a[mt], b[nt][0], b[nt][1]);
        }
        __syncthreads();
    }

    #pragma unroll
    for (int mt = 0; mt < 2; mt++) {
        const int trow = t0 + warp_m * 32 + mt * 16 + grp;
        #pragma unroll
        for (int nt = 0; nt < 4; nt++) {
            const int ncol = n0 + warp_n * 32 + nt * 8 + 2 * qd;
            *(float2*)&Y[(size_t)trow * Ntot + ncol] =
                make_float2(acc[mt][nt][0], acc[mt][nt][1]);
            *(float2*)&Y[(size_t)(trow + 8) * Ntot + ncol] =
                make_float2(acc[mt][nt][2], acc[mt][nt][3]);
        }
    }
}

// ---------------- split-K reduce (4 partials -> out) -----------------------
__global__ void __launch_bounds__(256) reduce4_kernel(float* __restrict__ out)
{
    const int i = blockIdx.x * 256 + threadIdx.x;         // float4 index
    const size_t S = (size_t)T_TOK * DOUT / 4;
    const float4* p = (const float4*)g_part;
    float4 a = p[i], b = p[i + S], c = p[i + 2 * S], d = p[i + 3 * S];
    float4 r;
    r.x = (a.x + b.x) + (c.x + d.x);
    r.y = (a.y + b.y) + (c.y + d.y);
    r.z = (a.z + b.z) + (c.z + d.z);
    r.w = (a.w + b.w) + (c.w + d.w);
    ((float4*)out)[i] = r;
}

// ---------------- rms_norm + sequence rope + platonic rope + transpose ----
__global__ void __launch_bounds__(256) rope_kernel(
    const float* __restrict__ coords, const int* __restrict__ seq_idx,
    const float* __restrict__ qnw, const float* __restrict__ knw,
    const float* __restrict__ pfreqs)
{
    const int t = blockIdx.x;
    const int b = t / SEQ, n = t % SEQ;
    const float cx = coords[t * 3 + 0];
    const float cy = coords[t * 3 + 1];
    const float cz = coords[t * 3 + 2];
    const float pos = (float)seq_idx[t];
    const float EPS = 1.1920929e-07f;
    const float LOG1E4_OV16 = 9.210340371976184f / 16.0f;

    for (int base = 0; base < GH * 16; base += 256) {
        const int p  = base + threadIdx.x;
        const int gh = p >> 4;
        const int f  = p & 15;
        const int g  = gh >> 3;
        const int h  = gh & 7;

        const int off = t * DQK + gh * 32 + 2 * f;
        float q1 = g_q[off], q2 = g_q[off + 1];
        float k1 = g_k[off], k2 = g_k[off + 1];

        float sq = q1 * q1 + q2 * q2;
        float sk = k1 * k1 + k2 * k2;
        #pragma unroll
        for (int o2 = 8; o2 > 0; o2 >>= 1) {
            sq += __shfl_xor_sync(0xffffffffu, sq, o2, 16);
            sk += __shfl_xor_sync(0xffffffffu, sk, o2, 16);
        }
        const float rq = rsqrtf(sq * (1.0f / 32.0f) + EPS);
        const float rk = rsqrtf(sk * (1.0f / 32.0f) + EPS);
        q1 *= rq * qnw[2 * f];  q2 *= rq * qnw[2 * f + 1];
        k1 *= rk * knw[2 * f];  k2 *= rk * knw[2 * f + 1];

        const float invf = expf(-(float)f * LOG1E4_OV16);
        const float ang  = pos * invf;

        const float th = 6.283185307179586f * (float)g * (1.0f / 12.0f);
        float sg, cg;  sincosf(th, &sg, &cg);
        const float c0 =  cx * cg + cy * sg;
        const float c1 = -cx * sg + cy * cg;
        const float* fr = pfreqs + (h * 16 + f) * 3;
        const float ph  = c0 * fr[0] + c1 * fr[1] + cz * fr[2];

        float s, c;  sincosf(ang + ph, &s, &c);
        const float qo1 = q1 * c - q2 * s, qo2 = q1 * s + q2 * c;
        const float ko1 = k1 * c - k2 * s, ko2 = k1 * s + k2 * c;

        const size_t dst = (((size_t)b * GH + gh) * SEQ + n) * 32 + 2 * f;
        g_qT[dst] = qo1;  g_qT[dst + 1] = qo2;
        g_kT[dst] = ko1;  g_kT[dst + 1] = ko2;
    }

    for (int i = threadIdx.x; i < DQK; i += 256) {
        const int gh = i >> 5, d = i & 31;
        g_vTd[(((size_t)b * GH + gh) * 32 + d) * SEQ + n] = g_v[(size_t)t * DQK + i];
    }
}

// ---------------- attention: flash-style tf32 MMA ---------------------------
#define KPAD 36
#define VPAD 516
#define ATTN_SMEM ((2*512*KPAD + 32*VPAD) * 4)

__global__ void __launch_bounds__(256) attn_mma_kernel()
{
    extern __shared__ uint32_t sh_u[];
    uint32_t* Khi = sh_u;
    uint32_t* Klo = sh_u + 512 * KPAD;
    uint32_t* Vt  = sh_u + 2 * 512 * KPAD;

    const int qc = blockIdx.x;
    const int gh = blockIdx.y;
    const int b  = blockIdx.z;
    const int tid  = threadIdx.x;
    const int wid  = tid >> 5;
    const int lane = tid & 31;
    const int grp  = lane >> 2;
    const int qd   = lane & 3;

    const size_t base  = (((size_t)b * GH + gh) * SEQ) * 32;
    const size_t vbase = (((size_t)b * GH + gh) * 32) * SEQ;

    {
        const int key0 = tid >> 3;
        const int c4   = (tid & 7) * 4;
        for (int key = key0; key < SEQ; key += 32) {
            float4 v = *(const float4*)(g_kT + base + (size_t)key * 32 + c4);
            uint32_t h0 = f2tf32(v.x), h1 = f2tf32(v.y);
            uint32_t h2 = f2tf32(v.z), h3 = f2tf32(v.w);
            uint32_t l0 = f2tf32(v.x - __uint_as_float(h0));
            uint32_t l1 = f2tf32(v.y - __uint_as_float(h1));
            uint32_t l2 = f2tf32(v.z - __uint_as_float(h2));
            uint32_t l3 = f2tf32(v.w - __uint_as_float(h3));
            *(uint4*)&Khi[key * KPAD + c4] = make_uint4(h0, h1, h2, h3);
            *(uint4*)&Klo[key * KPAD + c4] = make_uint4(l0, l1, l2, l3);
        }
        const int d0 = tid >> 3;
        for (int kk = (tid & 7) * 4; kk < SEQ; kk += 32) {
            float4 v = *(const float4*)(g_vTd + vbase + (size_t)d0 * SEQ + kk);
            *(uint4*)&Vt[d0 * VPAD + kk] =
                make_uint4(f2tf32(v.x), f2tf32(v.y), f2tf32(v.z), f2tf32(v.w));
        }
    }
    __syncthreads();

    const int qrow0 = qc * 256 + wid * 32;
    const float scale = 0.17677669529663687f;
    uint32_t qhi[2][4][4], qlo[2][4][4];
    #pragma unroll
    for (int mt = 0; mt < 2; mt++)
        #pragma unroll
        for (int ks = 0; ks < 4; ks++)
            #pragma unroll
            for (int e = 0; e < 4; e++) {
                const int row = mt * 16 + grp + (e & 1) * 8;
                const int col = ks * 8 + qd + (e >> 1) * 4;
                float x = g_qT[base + (size_t)(qrow0 + row) * 32 + col] * scale;
                uint32_t h = f2tf32(x);
                qhi[mt][ks][e] = h;
                qlo[mt][ks][e] = f2tf32(x - __uint_as_float(h));
            }

    float mrow[2][2], lrow[2][2];
    float o[2][4][4];
    #pragma unroll
    for (int mt = 0; mt < 2; mt++)
        #pragma unroll
        for (int h = 0; h < 2; h++) { mrow[mt][h] = -1e30f; lrow[mt][h] = 0.0f; }
    #pragma unroll
    for (int mt = 0; mt < 2; mt++)
        #pragma unroll
        for (int nt = 0; nt < 4; nt++)
            #pragma unroll
            for (int c = 0; c < 4; c++) o[mt][nt][c] = 0.0f;

    float s[2][8][4];

    for (int kt = 0; kt < 8; kt++) {
        #pragma unroll
        for (int mt = 0; mt < 2; mt++)
            #pragma unroll
            for (int nt = 0; nt < 8; nt++)
                #pragma unroll
                for (int c = 0; c < 4; c++) s[mt][nt][c] = 0.0f;

        #pragma unroll
        for (int ks = 0; ks < 4; ks++) {
            #pragma unroll
            for (int nt = 0; nt < 8; nt++) {
                const int key = kt * 64 + nt * 8 + grp;
                const int kc  = ks * 8 + qd;
                uint32_t bh0 = Khi[key * KPAD + kc];
                uint32_t bh1 = Khi[key * KPAD + kc + 4];
                uint32_t bl0 = Klo[key * KPAD + kc];
                uint32_t bl1 = Klo[key * KPAD + kc + 4];
                #pragma unroll
                for (int mt = 0; mt < 2; mt++) {
                    mma_tf32(s[mt][nt], qhi[mt][ks], bh0, bh1);
                    mma_tf32(s[mt][nt], qhi[mt][ks], bl0, bl1);
                    mma_tf32(s[mt][nt], qlo[mt][ks], bh0, bh1);
                }
            }
        }

        float esc[2][2];
        #pragma unroll
        for (int mt = 0; mt < 2; mt++)
            #pragma unroll
            for (int h = 0; h < 2; h++) {
                float mx = -1e30f;
                #pragma unroll
                for (int nt = 0; nt < 8; nt++)
                    mx = fmaxf(mx, fmaxf(s[mt][nt][2 * h], s[mt][nt][2 * h + 1]));
                mx = fmaxf(mx, __shfl_xor_sync(0xffffffffu, mx, 1));
                mx = fmaxf(mx, __shfl_xor_sync(0xffffffffu, mx, 2));
                const float mnew = fmaxf(mrow[mt][h], mx);
                esc[mt][h] = expf(mrow[mt][h] - mnew);
                mrow[mt][h] = mnew;
            }
        #pragma unroll
        for (int mt = 0; mt < 2; mt++)
            #pragma unroll
            for (int nt = 0; nt < 8; nt++)
                #pragma unroll
                for (int c = 0; c < 4; c++)
                    s[mt][nt][c] = expf(s[mt][nt][c] - mrow[mt][c >> 1]);
        #pragma unroll
        for (int mt = 0; mt < 2; mt++)
            #pragma unroll
            for (int h = 0; h < 2; h++) {
                float ps = 0.0f;
                #pragma unroll
                for (int nt = 0; nt < 8; nt++)
                    ps += s[mt][nt][2 * h] + s[mt][nt][2 * h + 1];
                ps += __shfl_xor_sync(0xffffffffu, ps, 1);
                ps += __shfl_xor_sync(0xffffffffu, ps, 2);
                lrow[mt][h] = lrow[mt][h] * esc[mt][h] + ps;
            }
        #pragma unroll
        for (int mt = 0; mt < 2; mt++)
            #pragma unroll
            for (int nt = 0; nt < 4; nt++)
                #pragma unroll
                for (int c = 0; c < 4; c++)
                    o[mt][nt][c] *= esc[mt][c >> 1];

        const int s1 = grp * 4 + (qd >> 1);
        const int s2 = s1 + 2;
        const bool odd = (qd & 1);
        #pragma unroll
        for (int ks = 0; ks < 8; ks++) {
            uint32_t a[2][4];
            #pragma unroll
            for (int mt = 0; mt < 2; mt++) {
                uint32_t u0 = f2tf32(s[mt][ks][0]);
                uint32_t u1 = f2tf32(s[mt][ks][1]);
                uint32_t u2 = f2tf32(s[mt][ks][2]);
                uint32_t u3 = f2tf32(s[mt][ks][3]);
                uint32_t v00 = __shfl_sync(0xffffffffu, u0, s1);
                uint32_t v01 = __shfl_sync(0xffffffffu, u1, s1);
                uint32_t v20 = __shfl_sync(0xffffffffu, u2, s1);
                uint32_t v21 = __shfl_sync(0xffffffffu, u3, s1);
                uint32_t w00 = __shfl_sync(0xffffffffu, u0, s2);
                uint32_t w01 = __shfl_sync(0xffffffffu, u1, s2);
                uint32_t w20 = __shfl_sync(0xffffffffu, u2, s2);
                uint32_t w21 = __shfl_sync(0xffffffffu, u3, s2);
                a[mt][0] = odd ? v01 : v00;
                a[mt][1] = odd ? v21 : v20;
                a[mt][2] = odd ? w01 : w00;
                a[mt][3] = odd ? w21 : w20;
            }
            #pragma unroll
            for (int nt = 0; nt < 4; nt++) {
                const int col = kt * 64 + ks * 8 + qd;
                uint32_t b0 = Vt[(nt * 8 + grp) * VPAD + col];
                uint32_t b1 = Vt[(nt * 8 + grp) * VPAD + col + 4];
                #pragma unroll
                for (int mt = 0; mt < 2; mt++)
                    mma_tf32(o[mt][nt], a[mt], b0, b1);
            }
        }
    }

    #pragma unroll
    for (int mt = 0; mt < 2; mt++) {
        const float inv0 = 1.0f / lrow[mt][0];
        const float inv1 = 1.0f / lrow[mt][1];
        const int n0 = qrow0 + mt * 16 + grp;
        #pragma unroll
        for (int nt = 0; nt < 4; nt++) {
            const int gcol = gh * 32 + nt * 8 + 2 * qd;
            *(float2*)&g_ao[((size_t)(b * SEQ + n0)) * DQK + gcol] =
                make_float2(o[mt][nt][0] * inv0, o[mt][nt][1] * inv0);
            *(float2*)&g_ao[((size_t)(b * SEQ + n0 + 8)) * DQK + gcol] =
                make_float2(o[mt][nt][2] * inv1, o[mt][nt][3] * inv1);
        }
    }
}

// ---------------- launch ---------------------------------------------------
#define GEMM_SMEM ((2*128*GPAD + 2*64*GPAD) * 4)   // 104448 B

extern "C" void kernel_launch(void* const* d_in, const int* in_sizes, int n_in,
                              void* d_out, int out_size)
{
    const float* feat   = (const float*)d_in[0];
    const float* coords = (const float*)d_in[1];
    const float* Wq     = (const float*)d_in[2];
    const float* Wk     = (const float*)d_in[3];
    const float* Wv     = (const float*)d_in[4];
    const float* Wo     = (const float*)d_in[5];
    const float* qnw    = (const float*)d_in[6];
    const float* knw    = (const float*)d_in[7];
    const float* pfrq   = (const float*)d_in[8];
    const int*   sidx   = (const int*)d_in[9];
    float* out = (float*)d_out;

    void *pq, *pk, *pv, *pao, *ppart;
    cudaGetSymbolAddress(&pq,   g_q);
    cudaGetSymbolAddress(&pk,   g_k);
    cudaGetSymbolAddress(&pv,   g_v);
    cudaGetSymbolAddress(&pao,  g_ao);
    cudaGetSymbolAddress(&ppart, g_part);

    cudaFuncSetAttribute(circ_gemm2<H * CQK, CIN, 1>,
                         cudaFuncAttributeMaxDynamicSharedMemorySize, GEMM_SMEM);
    cudaFuncSetAttribute(circ_gemm2<COUT, H * CVAL, 4>,
                         cudaFuncAttributeMaxDynamicSharedMemorySize, GEMM_SMEM);
    cudaFuncSetAttribute(attn_mma_kernel,
                         cudaFuncAttributeMaxDynamicSharedMemorySize, ATTN_SMEM);

    // fused QKV projections: z = problem {Wq,Wk,Wv}
    circ_gemm2<H * CQK, CIN, 1>
        <<<dim3(DQK / 64, T_TOK / 128, 3), 256, GEMM_SMEM>>>(
        feat, Wq, Wk, Wv, (float*)pq, (float*)pk, (float*)pv);

    // norm + ropes + transpose
    rope_kernel<<<T_TOK, 256>>>(coords, sidx, qnw, knw, pfrq);

    // attention
    attn_mma_kernel<<<dim3(2, GH, BATCH), 256, ATTN_SMEM>>>();

    // output projection, split-K=4 into partials, then reduce
    circ_gemm2<COUT, H * CVAL, 4>
        <<<dim3(DOUT / 64, T_TOK / 128, 4), 256, GEMM_SMEM>>>(
        (const float*)pao, Wo, Wo, Wo, (float*)ppart, (float*)ppart, (float*)ppart);
    reduce4_kernel<<<T_TOK * DOUT / 4 / 256, 256>>>(out);
}

// round 9
// speedup vs baseline: 3.7721x; 1.1321x over previous
#include <cuda_runtime.h>
#include <cuda_fp16.h>
#include <math.h>
#include <stdint.h>

#define G    12
#define H    8
#define CQK  32
#define CVAL 32
#define CIN  64
#define COUT 64
#define BATCH 2
#define SEQ  512
#define T_TOK (BATCH*SEQ)   // 1024 tokens
#define DIN  (G*CIN)        // 768
#define DQK  (G*H*CQK)      // 3072
#define GH   (G*H)          // 96
#define DOUT (G*COUT)       // 768

// ---------------- scratch (device globals; no allocation allowed) ----------
__device__ float g_q  [T_TOK*DQK];
__device__ float g_k  [T_TOK*DQK];
__device__ float g_v  [T_TOK*DQK];
__device__ float g_qT [T_TOK*DQK];   // [b][gh][n][32]
__device__ float g_kT [T_TOK*DQK];   // [b][gh][n][32]
__device__ float g_vTd[T_TOK*DQK];   // [b][gh][d][n]
__device__ float g_ao [T_TOK*DQK];   // attention out, token-major
__device__ float g_part[4*T_TOK*DOUT]; // Wo split-K partials

__device__ __forceinline__ uint32_t f2tf32(float x) {
    uint32_t u;
    asm("cvt.rna.tf32.f32 %0, %1;" : "=r"(u) : "f"(x));
    return u;
}
__device__ __forceinline__ uint32_t u2tf32(uint32_t u) {
    return f2tf32(__uint_as_float(u));
}

__device__ __forceinline__ void mma_tf32(float* c, const uint32_t* a,
                                         uint32_t b0, uint32_t b1) {
    asm volatile(
        "mma.sync.aligned.m16n8k8.row.col.f32.tf32.tf32.f32 "
        "{%0,%1,%2,%3}, {%4,%5,%6,%7}, {%8,%9}, {%0,%1,%2,%3};"
        : "+f"(c[0]), "+f"(c[1]), "+f"(c[2]), "+f"(c[3])
        : "r"(a[0]), "r"(a[1]), "r"(a[2]), "r"(a[3]), "r"(b0), "r"(b1));
}

__device__ __forceinline__ void mma_f16(float* c, const uint32_t* a,
                                        uint32_t b0, uint32_t b1) {
    asm volatile(
        "mma.sync.aligned.m16n8k16.row.col.f32.f16.f16.f32 "
        "{%0,%1,%2,%3}, {%4,%5,%6,%7}, {%8,%9}, {%0,%1,%2,%3};"
        : "+f"(c[0]), "+f"(c[1]), "+f"(c[2]), "+f"(c[3])
        : "r"(a[0]), "r"(a[1]), "r"(a[2]), "r"(a[3]), "r"(b0), "r"(b1));
}

__device__ __forceinline__ void ldsm4(uint32_t& r0, uint32_t& r1,
                                      uint32_t& r2, uint32_t& r3,
                                      const void* p) {
    uint32_t a = (uint32_t)__cvta_generic_to_shared(p);
    asm volatile("ldmatrix.sync.aligned.m8n8.x4.shared.b16 {%0,%1,%2,%3}, [%4];"
                 : "=r"(r0), "=r"(r1), "=r"(r2), "=r"(r3) : "r"(a));
}

__device__ __forceinline__ void cpa16(float* smem, const float* gmem) {
    uint32_t s = (uint32_t)__cvta_generic_to_shared(smem);
    asm volatile("cp.async.cg.shared.global [%0], [%1], 16;" :: "r"(s), "l"(gmem));
}

__device__ __forceinline__ uint32_t packh2(float a, float b) {
    half2 h = __floats2half2_rn(a, b);
    return *reinterpret_cast<uint32_t*>(&h);
}
__device__ __forceinline__ void pack_hilo(float a, float b,
                                          uint32_t& hi, uint32_t& lo) {
    half2 h = __floats2half2_rn(a, b);
    float2 hf = __half22float2(h);
    half2 l = __floats2half2_rn(a - hf.x, b - hf.y);
    hi = *reinterpret_cast<uint32_t*>(&h);
    lo = *reinterpret_cast<uint32_t*>(&l);
}

// ---------------- block-circulant GEMM: cp.async + ldmatrix tf32 ------------
// Y[t][go*CO+o] = sum_{gi,i} X[t][gi*CI+i] * W[(gi-go)%G][o][i]
// BM=128 x BN=64 x BK=64, 8 warps = 4(M) x 2(N), warp tile 32x32.
#define GPAD 68
template<int CO, int CI, int KSPLIT>
__global__ void __launch_bounds__(256) circ_gemm2(
    const float* __restrict__ X,
    const float* __restrict__ W0, const float* __restrict__ W1,
    const float* __restrict__ W2,
    float* __restrict__ Y0, float* __restrict__ Y1, float* __restrict__ Y2)
{
    constexpr int BM   = 128;
    constexpr int BK   = 64;
    constexpr int Ktot = G * CI;
    constexpr int Ntot = G * CO;
    constexpr int Kper = Ktot / KSPLIT;
    constexpr int NIT  = Kper / BK;

    extern __shared__ float sm[];
    float* As = sm;                 // [2][BM][GPAD]
    float* Bs = sm + 2 * BM * GPAD; // [2][64][GPAD]

    const int z    = blockIdx.z;
    const int prob = (KSPLIT == 1) ? z : 0;
    const int ksl  = (KSPLIT == 1) ? 0 : z;
    const float* W = (prob == 0) ? W0 : (prob == 1) ? W1 : W2;
    float* Y = ((prob == 0) ? Y0 : (prob == 1) ? Y1 : Y2)
               + (size_t)ksl * T_TOK * Ntot;

    const int tid = threadIdx.x;
    const int n0 = blockIdx.x * 64;
    const int t0 = blockIdx.y * BM;
    const int go = n0 / CO;
    const int o0 = n0 % CO;

    const int wid    = tid >> 5;
    const int lane   = tid & 31;
    const int warp_m = wid & 3;
    const int warp_n = wid >> 2;
    const int grp    = lane >> 2;
    const int qd     = lane & 3;

    // ldmatrix per-lane address pieces
    const int a_lrow = lane & 15;
    const int a_lcol = (lane >> 4) * 4;
    const int b_lrow = ((lane >> 4) << 3) + (lane & 7);
    const int b_lcol = ((lane >> 3) & 1) * 4;

    const int kbeg = ksl * Kper;

    auto load_tile = [&](int buf, int kk) {
        const int gi = kk / CI;
        const int i0 = kk % CI;
        const int wg = (gi - go + G) % G;
        const float* Xb = X + (size_t)t0 * Ktot + kk;
        const float* Wb = W + ((size_t)wg * CO + o0) * CI + i0;
        float* Ab = As + buf * BM * GPAD;
        float* Bb = Bs + buf * 64 * GPAD;
        #pragma unroll
        for (int i = 0; i < 8; i++) {
            const int ch  = tid + i * 256;
            const int row = ch >> 4;
            const int c4  = (ch & 15) << 2;
            cpa16(Ab + row * GPAD + c4, Xb + (size_t)row * Ktot + c4);
        }
        #pragma unroll
        for (int i = 0; i < 4; i++) {
            const int ch  = tid + i * 256;
            const int row = ch >> 4;
            const int c4  = (ch & 15) << 2;
            cpa16(Bb + row * GPAD + c4, Wb + (size_t)row * CI + c4);
        }
        asm volatile("cp.async.commit_group;");
    };

    float acc[2][4][4];
    #pragma unroll
    for (int mt = 0; mt < 2; mt++)
        #pragma unroll
        for (int nt = 0; nt < 4; nt++)
            #pragma unroll
            for (int i = 0; i < 4; i++) acc[mt][nt][i] = 0.0f;

    load_tile(0, kbeg);

    for (int it = 0; it < NIT; it++) {
        if (it + 1 < NIT) {
            load_tile((it + 1) & 1, kbeg + (it + 1) * BK);
            asm volatile("cp.async.wait_group 1;");
        } else {
            asm volatile("cp.async.wait_group 0;");
        }
        __syncthreads();

        const float* Ab = As + (it & 1) * BM * GPAD;
        const float* Bb = Bs + (it & 1) * 64 * GPAD;

        #pragma unroll
        for (int ks = 0; ks < 8; ks++) {
            const int kb = ks * 8;
            uint32_t a[2][4], b[4][2];
            #pragma unroll
            for (int mt = 0; mt < 2; mt++) {
                ldsm4(a[mt][0], a[mt][1], a[mt][2], a[mt][3],
                      Ab + (warp_m * 32 + mt * 16 + a_lrow) * GPAD + kb + a_lcol);
                #pragma unroll
                for (int e = 0; e < 4; e++) a[mt][e] = u2tf32(a[mt][e]);
            }
            #pragma unroll
            for (int np = 0; np < 2; np++) {
                uint32_t r0, r1, r2, r3;
                ldsm4(r0, r1, r2, r3,
                      Bb + (warp_n * 32 + np * 16 + b_lrow) * GPAD + kb + b_lcol);
                b[np * 2    ][0] = u2tf32(r0);
                b[np * 2    ][1] = u2tf32(r1);
                b[np * 2 + 1][0] = u2tf32(r2);
                b[np * 2 + 1][1] = u2tf32(r3);
            }
            #pragma unroll
            for (int mt = 0; mt < 2; mt++)
                #pragma unroll
                for (int nt = 0; nt < 4; nt++)
                    mma_tf32(acc[mt][nt], a[mt], b[nt][0], b[nt][1]);
        }
        __syncthreads();
    }

    #pragma unroll
    for (int mt = 0; mt < 2; mt++) {
        const int trow = t0 + warp_m * 32 + mt * 16 + grp;
        #pragma unroll
        for (int nt = 0; nt < 4; nt++) {
            const int ncol = n0 + warp_n * 32 + nt * 8 + 2 * qd;
            *(float2*)&Y[(size_t)trow * Ntot + ncol] =
                make_float2(acc[mt][nt][0], acc[mt][nt][1]);
            *(float2*)&Y[(size_t)(trow + 8) * Ntot + ncol] =
                make_float2(acc[mt][nt][2], acc[mt][nt][3]);
        }
    }
}

// ---------------- split-K reduce (4 partials -> out) -----------------------
__global__ void __launch_bounds__(256) reduce4_kernel(float* __restrict__ out)
{
    const int i = blockIdx.x * 256 + threadIdx.x;
    const size_t S = (size_t)T_TOK * DOUT / 4;
    const float4* p = (const float4*)g_part;
    float4 a = p[i], b = p[i + S], c = p[i + 2 * S], d = p[i + 3 * S];
    float4 r;
    r.x = (a.x + b.x) + (c.x + d.x);
    r.y = (a.y + b.y) + (c.y + d.y);
    r.z = (a.z + b.z) + (c.z + d.z);
    r.w = (a.w + b.w) + (c.w + d.w);
    ((float4*)out)[i] = r;
}

// ---------------- rms_norm + sequence rope + platonic rope + transpose ----
__global__ void __launch_bounds__(256) rope_kernel(
    const float* __restrict__ coords, const int* __restrict__ seq_idx,
    const float* __restrict__ qnw, const float* __restrict__ knw,
    const float* __restrict__ pfreqs)
{
    const int t = blockIdx.x;
    const int b = t / SEQ, n = t % SEQ;
    const float cx = coords[t * 3 + 0];
    const float cy = coords[t * 3 + 1];
    const float cz = coords[t * 3 + 2];
    const float pos = (float)seq_idx[t];
    const float EPS = 1.1920929e-07f;
    const float LOG1E4_OV16 = 9.210340371976184f / 16.0f;

    for (int base = 0; base < GH * 16; base += 256) {
        const int p  = base + threadIdx.x;
        const int gh = p >> 4;
        const int f  = p & 15;
        const int g  = gh >> 3;
        const int h  = gh & 7;

        const int off = t * DQK + gh * 32 + 2 * f;
        float q1 = g_q[off], q2 = g_q[off + 1];
        float k1 = g_k[off], k2 = g_k[off + 1];

        float sq = q1 * q1 + q2 * q2;
        float sk = k1 * k1 + k2 * k2;
        #pragma unroll
        for (int o2 = 8; o2 > 0; o2 >>= 1) {
            sq += __shfl_xor_sync(0xffffffffu, sq, o2, 16);
            sk += __shfl_xor_sync(0xffffffffu, sk, o2, 16);
        }
        const float rq = rsqrtf(sq * (1.0f / 32.0f) + EPS);
        const float rk = rsqrtf(sk * (1.0f / 32.0f) + EPS);
        q1 *= rq * qnw[2 * f];  q2 *= rq * qnw[2 * f + 1];
        k1 *= rk * knw[2 * f];  k2 *= rk * knw[2 * f + 1];

        const float invf = __expf(-(float)f * LOG1E4_OV16);
        const float ang  = pos * invf;

        const float th = 6.283185307179586f * (float)g * (1.0f / 12.0f);
        float sg, cg;  __sincosf(th, &sg, &cg);
        const float c0 =  cx * cg + cy * sg;
        const float c1 = -cx * sg + cy * cg;
        const float* fr = pfreqs + (h * 16 + f) * 3;
        const float ph  = c0 * fr[0] + c1 * fr[1] + cz * fr[2];

        float s, c;  sincosf(ang + ph, &s, &c);
        const float qo1 = q1 * c - q2 * s, qo2 = q1 * s + q2 * c;
        const float ko1 = k1 * c - k2 * s, ko2 = k1 * s + k2 * c;

        const size_t dst = (((size_t)b * GH + gh) * SEQ + n) * 32 + 2 * f;
        g_qT[dst] = qo1;  g_qT[dst + 1] = qo2;
        g_kT[dst] = ko1;  g_kT[dst + 1] = ko2;
    }

    for (int i = threadIdx.x; i < DQK; i += 256) {
        const int gh = i >> 5, d = i & 31;
        g_vTd[(((size_t)b * GH + gh) * 32 + d) * SEQ + n] = g_v[(size_t)t * DQK + i];
    }
}

// ---------------- attention: flash tf32 QK^T (3xTF32) + fp16 PV -------------
// K hi/lo tf32 in smem (ldmatrix frags); P split hi+lo fp16 -> m16n8k16 PV
// with zero shuffles (C-frag pairs == A-frag half2 layout). V fp16 in smem.
#define KPAD 36
#define VP2  260    // half2 row stride for Vh (stride mod 32 banks = 4)
#define ATTN_SMEM ((2*512*KPAD + 32*VP2) * 4)

__global__ void __launch_bounds__(256) attn_mma_kernel()
{
    extern __shared__ uint32_t sh_u[];
    uint32_t* Khi = sh_u;
    uint32_t* Klo = sh_u + 512 * KPAD;
    uint32_t* Vh  = sh_u + 2 * 512 * KPAD;   // half2 [32][VP2]

    const int qc = blockIdx.x;
    const int gh = blockIdx.y;
    const int b  = blockIdx.z;
    const int tid  = threadIdx.x;
    const int wid  = tid >> 5;
    const int lane = tid & 31;
    const int grp  = lane >> 2;
    const int qd   = lane & 3;

    const size_t base  = (((size_t)b * GH + gh) * SEQ) * 32;
    const size_t vbase = (((size_t)b * GH + gh) * 32) * SEQ;

    // ---- prologue ----
    {
        const int key0 = tid >> 3;
        const int c4   = (tid & 7) * 4;
        for (int key = key0; key < SEQ; key += 32) {
            float4 v = *(const float4*)(g_kT + base + (size_t)key * 32 + c4);
            uint32_t h0 = f2tf32(v.x), h1 = f2tf32(v.y);
            uint32_t h2 = f2tf32(v.z), h3 = f2tf32(v.w);
            uint32_t l0 = f2tf32(v.x - __uint_as_float(h0));
            uint32_t l1 = f2tf32(v.y - __uint_as_float(h1));
            uint32_t l2 = f2tf32(v.z - __uint_as_float(h2));
            uint32_t l3 = f2tf32(v.w - __uint_as_float(h3));
            *(uint4*)&Khi[key * KPAD + c4] = make_uint4(h0, h1, h2, h3);
            *(uint4*)&Klo[key * KPAD + c4] = make_uint4(l0, l1, l2, l3);
        }
        const int d0 = tid >> 3;
        for (int kk = (tid & 7) * 8; kk < SEQ; kk += 64) {
            float4 v0 = *(const float4*)(g_vTd + vbase + (size_t)d0 * SEQ + kk);
            float4 v1 = *(const float4*)(g_vTd + vbase + (size_t)d0 * SEQ + kk + 4);
            uint32_t* dst = Vh + d0 * VP2 + (kk >> 1);
            dst[0] = packh2(v0.x, v0.y);
            dst[1] = packh2(v0.z, v0.w);
            dst[2] = packh2(v1.x, v1.y);
            dst[3] = packh2(v1.z, v1.w);
        }
    }
    __syncthreads();

    // ---- per-warp Q fragments (scaled, hi/lo split) ----
    const int qrow0 = qc * 256 + wid * 32;
    const float scale = 0.17677669529663687f;
    uint32_t qhi[2][4][4], qlo[2][4][4];
    #pragma unroll
    for (int mt = 0; mt < 2; mt++)
        #pragma unroll
        for (int ks = 0; ks < 4; ks++)
            #pragma unroll
            for (int e = 0; e < 4; e++) {
                const int row = mt * 16 + grp + (e & 1) * 8;
                const int col = ks * 8 + qd + (e >> 1) * 4;
                float x = g_qT[base + (size_t)(qrow0 + row) * 32 + col] * scale;
                uint32_t hh = f2tf32(x);
                qhi[mt][ks][e] = hh;
                qlo[mt][ks][e] = f2tf32(x - __uint_as_float(hh));
            }

    // ldmatrix lane address pieces for K fragments
    const int bk_lrow = ((lane >> 4) << 3) + (lane & 7);
    const int bk_lcol = ((lane >> 3) & 1) * 4;

    float mrow[2][2], lrow[2][2];
    float o[2][4][4];
    #pragma unroll
    for (int mt = 0; mt < 2; mt++)
        #pragma unroll
        for (int h = 0; h < 2; h++) { mrow[mt][h] = -1e30f; lrow[mt][h] = 0.0f; }
    #pragma unroll
    for (int mt = 0; mt < 2; mt++)
        #pragma unroll
        for (int nt = 0; nt < 4; nt++)
            #pragma unroll
            for (int c = 0; c < 4; c++) o[mt][nt][c] = 0.0f;

    float s[2][8][4];

    for (int kt = 0; kt < 8; kt++) {        // 8 key tiles of 64
        #pragma unroll
        for (int mt = 0; mt < 2; mt++)
            #pragma unroll
            for (int nt = 0; nt < 8; nt++)
                #pragma unroll
                for (int c = 0; c < 4; c++) s[mt][nt][c] = 0.0f;

        // ---- QK^T (3xTF32), ldmatrix K fragments ----
        #pragma unroll
        for (int ks = 0; ks < 4; ks++) {
            const int kb = ks * 8;
            #pragma unroll
            for (int jp = 0; jp < 4; jp++) {
                const int krow = kt * 64 + jp * 16 + bk_lrow;
                uint32_t bh0, bh1, bh2, bh3, bl0, bl1, bl2, bl3;
                ldsm4(bh0, bh1, bh2, bh3, Khi + krow * KPAD + kb + bk_lcol);
                ldsm4(bl0, bl1, bl2, bl3, Klo + krow * KPAD + kb + bk_lcol);
                #pragma unroll
                for (int mt = 0; mt < 2; mt++) {
                    mma_tf32(s[mt][jp * 2    ], qhi[mt][ks], bh0, bh1);
                    mma_tf32(s[mt][jp * 2    ], qhi[mt][ks], bl0, bl1);
                    mma_tf32(s[mt][jp * 2    ], qlo[mt][ks], bh0, bh1);
                    mma_tf32(s[mt][jp * 2 + 1], qhi[mt][ks], bh2, bh3);
                    mma_tf32(s[mt][jp * 2 + 1], qhi[mt][ks], bl2, bl3);
                    mma_tf32(s[mt][jp * 2 + 1], qlo[mt][ks], bh2, bh3);
                }
            }
        }

        // ---- online softmax ----
        float esc[2][2];
        #pragma unroll
        for (int mt = 0; mt < 2; mt++)
            #pragma unroll
            for (int h = 0; h < 2; h++) {
                float mx = -1e30f;
                #pragma unroll
                for (int nt = 0; nt < 8; nt++)
                    mx = fmaxf(mx, fmaxf(s[mt][nt][2 * h], s[mt][nt][2 * h + 1]));
                mx = fmaxf(mx, __shfl_xor_sync(0xffffffffu, mx, 1));
                mx = fmaxf(mx, __shfl_xor_sync(0xffffffffu, mx, 2));
                const float mnew = fmaxf(mrow[mt][h], mx);
                esc[mt][h] = __expf(mrow[mt][h] - mnew);
                mrow[mt][h] = mnew;
            }
        #pragma unroll
        for (int mt = 0; mt < 2; mt++)
            #pragma unroll
            for (int nt = 0; nt < 8; nt++)
                #pragma unroll
                for (int c = 0; c < 4; c++)
                    s[mt][nt][c] = __expf(s[mt][nt][c] - mrow[mt][c >> 1]);
        #pragma unroll
        for (int mt = 0; mt < 2; mt++)
            #pragma unroll
            for (int h = 0; h < 2; h++) {
                float ps = 0.0f;
                #pragma unroll
                for (int nt = 0; nt < 8; nt++)
                    ps += s[mt][nt][2 * h] + s[mt][nt][2 * h + 1];
                ps += __shfl_xor_sync(0xffffffffu, ps, 1);
                ps += __shfl_xor_sync(0xffffffffu, ps, 2);
                lrow[mt][h] = lrow[mt][h] * esc[mt][h] + ps;
            }
        #pragma unroll
        for (int mt = 0; mt < 2; mt++)
            #pragma unroll
            for (int nt = 0; nt < 4; nt++)
                #pragma unroll
                for (int c = 0; c < 4; c++)
                    o[mt][nt][c] *= esc[mt][c >> 1];

        // ---- P·V (fp16 m16n8k16, P = hi+lo, shuffle-free) ----
        #pragma unroll
        for (int j = 0; j < 4; j++) {       // 16-key sub-blocks
            const int pb = kt * 32 + j * 8; // half2 column base
            uint32_t vb0[4], vb1[4];
            #pragma unroll
            for (int nt = 0; nt < 4; nt++) {
                vb0[nt] = Vh[(nt * 8 + grp) * VP2 + pb + qd];
                vb1[nt] = Vh[(nt * 8 + grp) * VP2 + pb + qd + 4];
            }
            #pragma unroll
            for (int mt = 0; mt < 2; mt++) {
                uint32_t ah[4], al[4];
                pack_hilo(s[mt][2*j  ][0], s[mt][2*j  ][1], ah[0], al[0]);
                pack_hilo(s[mt][2*j  ][2], s[mt][2*j  ][3], ah[1], al[1]);
                pack_hilo(s[mt][2*j+1][0], s[mt][2*j+1][1], ah[2], al[2]);
                pack_hilo(s[mt][2*j+1][2], s[mt][2*j+1][3], ah[3], al[3]);
                #pragma unroll
                for (int nt = 0; nt < 4; nt++) {
                    mma_f16(o[mt][nt], ah, vb0[nt], vb1[nt]);
                    mma_f16(o[mt][nt], al, vb0[nt], vb1[nt]);
                }
            }
        }
    }

    // ---- epilogue ----
    #pragma unroll
    for (int mt = 0; mt < 2; mt++) {
        const float inv0 = 1.0f / lrow[mt][0];
        const float inv1 = 1.0f / lrow[mt][1];
        const int n0 = qrow0 + mt * 16 + grp;
        #pragma unroll
        for (int nt = 0; nt < 4; nt++) {
            const int gcol = gh * 32 + nt * 8 + 2 * qd;
            *(float2*)&g_ao[((size_t)(b * SEQ + n0)) * DQK + gcol] =
                make_float2(o[mt][nt][0] * inv0, o[mt][nt][1] * inv0);
            *(float2*)&g_ao[((size_t)(b * SEQ + n0 + 8)) * DQK + gcol] =
                make_float2(o[mt][nt][2] * inv1, o[mt][nt][3] * inv1);
        }
    }
}

// ---------------- launch ---------------------------------------------------
#define GEMM_SMEM ((2*128*GPAD + 2*64*GPAD) * 4)   // 104448 B

extern "C" void kernel_launch(void* const* d_in, const int* in_sizes, int n_in,
                              void* d_out, int out_size)
{
    const float* feat   = (const float*)d_in[0];
    const float* coords = (const float*)d_in[1];
    const float* Wq     = (const float*)d_in[2];
    const float* Wk     = (const float*)d_in[3];
    const float* Wv     = (const float*)d_in[4];
    const float* Wo     = (const float*)d_in[5];
    const float* qnw    = (const float*)d_in[6];
    const float* knw    = (const float*)d_in[7];
    const float* pfrq   = (const float*)d_in[8];
    const int*   sidx   = (const int*)d_in[9];
    float* out = (float*)d_out;

    void *pq, *pk, *pv, *pao, *ppart;
    cudaGetSymbolAddress(&pq,   g_q);
    cudaGetSymbolAddress(&pk,   g_k);
    cudaGetSymbolAddress(&pv,   g_v);
    cudaGetSymbolAddress(&pao,  g_ao);
    cudaGetSymbolAddress(&ppart, g_part);

    cudaFuncSetAttribute(circ_gemm2<H * CQK, CIN, 1>,
                         cudaFuncAttributeMaxDynamicSharedMemorySize, GEMM_SMEM);
    cudaFuncSetAttribute(circ_gemm2<COUT, H * CVAL, 4>,
                         cudaFuncAttributeMaxDynamicSharedMemorySize, GEMM_SMEM);
    cudaFuncSetAttribute(attn_mma_kernel,
                         cudaFuncAttributeMaxDynamicSharedMemorySize, ATTN_SMEM);

    // fused QKV projections: z = problem {Wq,Wk,Wv}
    circ_gemm2<H * CQK, CIN, 1>
        <<<dim3(DQK / 64, T_TOK / 128, 3), 256, GEMM_SMEM>>>(
        feat, Wq, Wk, Wv, (float*)pq, (float*)pk, (float*)pv);

    // norm + ropes + transpose
    rope_kernel<<<T_TOK, 256>>>(coords, sidx, qnw, knw, pfrq);

    // attention
    attn_mma_kernel<<<dim3(2, GH, BATCH), 256, ATTN_SMEM>>>();

    // output projection, split-K=4 into partials, then reduce
    circ_gemm2<COUT, H * CVAL, 4>
        <<<dim3(DOUT / 64, T_TOK / 128, 4), 256, GEMM_SMEM>>>(
        (const float*)pao, Wo, Wo, Wo, (float*)ppart, (float*)ppart, (float*)ppart);
    reduce4_kernel<<<T_TOK * DOUT / 4 / 256, 256>>>(out);
}

// round 10
// speedup vs baseline: 5.3222x; 1.4110x over previous
#include <cuda_runtime.h>
#include <cuda_fp16.h>
#include <math.h>
#include <stdint.h>

#define G    12
#define H    8
#define CQK  32
#define CVAL 32
#define CIN  64
#define COUT 64
#define BATCH 2
#define SEQ  512
#define T_TOK (BATCH*SEQ)   // 1024 tokens
#define DIN  (G*CIN)        // 768
#define DQK  (G*H*CQK)      // 3072
#define GH   (G*H)          // 96
#define DOUT (G*COUT)       // 768

// ---------------- scratch (device globals; no allocation allowed) ----------
__device__ float  g_qT [T_TOK*DQK];                    // [b][gh][n][32] fp32
__device__ __align__(16) __half g_khi[T_TOK*DQK];      // [b][gh][n][32] fp16 hi
__device__ __align__(16) __half g_klo[T_TOK*DQK];      // fp16 lo residual
__device__ __align__(16) __half g_vh [T_TOK*DQK];      // [b][gh][n][32] fp16
__device__ float  g_ao [T_TOK*DQK];                    // attention out, token-major
__device__ float  g_part[4*T_TOK*DOUT];                // Wo split-K partials

__device__ __forceinline__ uint32_t f2tf32(float x) {
    uint32_t u;
    asm("cvt.rna.tf32.f32 %0, %1;" : "=r"(u) : "f"(x));
    return u;
}
__device__ __forceinline__ uint32_t u2tf32(uint32_t u) {
    return f2tf32(__uint_as_float(u));
}

__device__ __forceinline__ void mma_tf32(float* c, const uint32_t* a,
                                         uint32_t b0, uint32_t b1) {
    asm volatile(
        "mma.sync.aligned.m16n8k8.row.col.f32.tf32.tf32.f32 "
        "{%0,%1,%2,%3}, {%4,%5,%6,%7}, {%8,%9}, {%0,%1,%2,%3};"
        : "+f"(c[0]), "+f"(c[1]), "+f"(c[2]), "+f"(c[3])
        : "r"(a[0]), "r"(a[1]), "r"(a[2]), "r"(a[3]), "r"(b0), "r"(b1));
}
__device__ __forceinline__ void mma_f16(float* c, const uint32_t* a,
                                        uint32_t b0, uint32_t b1) {
    asm volatile(
        "mma.sync.aligned.m16n8k16.row.col.f32.f16.f16.f32 "
        "{%0,%1,%2,%3}, {%4,%5,%6,%7}, {%8,%9}, {%0,%1,%2,%3};"
        : "+f"(c[0]), "+f"(c[1]), "+f"(c[2]), "+f"(c[3])
        : "r"(a[0]), "r"(a[1]), "r"(a[2]), "r"(a[3]), "r"(b0), "r"(b1));
}
__device__ __forceinline__ void ldsm4(uint32_t& r0, uint32_t& r1,
                                      uint32_t& r2, uint32_t& r3, const void* p) {
    uint32_t a = (uint32_t)__cvta_generic_to_shared(p);
    asm volatile("ldmatrix.sync.aligned.m8n8.x4.shared.b16 {%0,%1,%2,%3}, [%4];"
                 : "=r"(r0), "=r"(r1), "=r"(r2), "=r"(r3) : "r"(a));
}
__device__ __forceinline__ void ldsm4t(uint32_t& r0, uint32_t& r1,
                                       uint32_t& r2, uint32_t& r3, const void* p) {
    uint32_t a = (uint32_t)__cvta_generic_to_shared(p);
    asm volatile("ldmatrix.sync.aligned.m8n8.x4.trans.shared.b16 {%0,%1,%2,%3}, [%4];"
                 : "=r"(r0), "=r"(r1), "=r"(r2), "=r"(r3) : "r"(a));
}
__device__ __forceinline__ void cpa16(void* smem, const void* gmem) {
    uint32_t s = (uint32_t)__cvta_generic_to_shared(smem);
    asm volatile("cp.async.cg.shared.global [%0], [%1], 16;" :: "r"(s), "l"(gmem));
}
__device__ __forceinline__ void pack_hilo(float a, float b,
                                          uint32_t& hi, uint32_t& lo) {
    half2 h = __floats2half2_rn(a, b);
    float2 hf = __half22float2(h);
    half2 l = __floats2half2_rn(a - hf.x, b - hf.y);
    hi = *reinterpret_cast<uint32_t*>(&h);
    lo = *reinterpret_cast<uint32_t*>(&l);
}

#define EPS 1.1920929e-07f
#define LOG1E4_OV16 (9.210340371976184f / 16.0f)

// ---------------- QKV GEMM with fused rms_norm + ropes ----------------------
// BM=128 x BN=64 x BK=32, double-buffered cp.async, tf32 mma.
// z selects {Q,K,V}. Epilogue: each warp's 32-col tile = one full head.
#define GPAD2 36
#define GEMM_SMEM ((2*128*GPAD2 + 2*64*GPAD2) * 4)   // 55296 B

__global__ void __launch_bounds__(256, 3) qkv_gemm(
    const float* __restrict__ X,
    const float* __restrict__ W0, const float* __restrict__ W1,
    const float* __restrict__ W2,
    const float* __restrict__ coords, const int* __restrict__ seq_idx,
    const float* __restrict__ qnw, const float* __restrict__ knw,
    const float* __restrict__ pfreqs)
{
    constexpr int CO = 256, CI = 64, BK = 32;
    constexpr int Ktot = G * CI;       // 768
    constexpr int NIT  = Ktot / BK;    // 24

    extern __shared__ float sm[];
    float* As = sm;                      // [2][128][GPAD2]
    float* Bs = sm + 2 * 128 * GPAD2;    // [2][64][GPAD2]

    const int prob = blockIdx.z;
    const float* W = (prob == 0) ? W0 : (prob == 1) ? W1 : W2;

    const int tid = threadIdx.x;
    const int n0 = blockIdx.x * 64;
    const int t0 = blockIdx.y * 128;
    const int go = n0 / CO;
    const int o0 = n0 % CO;

    const int wid    = tid >> 5;
    const int lane   = tid & 31;
    const int warp_m = wid & 3;
    const int warp_n = wid >> 2;
    const int grp    = lane >> 2;
    const int qd     = lane & 3;

    const int a_lrow = lane & 15;
    const int a_lcol = (lane >> 4) * 4;
    const int b_lrow = ((lane >> 4) << 3) + (lane & 7);
    const int b_lcol = ((lane >> 3) & 1) * 4;

    auto load_tile = [&](int buf, int kk) {
        const int gi = kk / CI;
        const int i0 = kk % CI;
        const int wg = (gi - go + G) % G;
        const float* Xb = X + (size_t)t0 * Ktot + kk;
        const float* Wb = W + ((size_t)wg * CO + o0) * CI + i0;
        float* Ab = As + buf * 128 * GPAD2;
        float* Bb = Bs + buf * 64 * GPAD2;
        #pragma unroll
        for (int i = 0; i < 4; i++) {           // 128 rows x 8 chunks = 1024
            const int ch  = tid + i * 256;
            const int row = ch >> 3;
            const int c4  = (ch & 7) << 2;
            cpa16(Ab + row * GPAD2 + c4, Xb + (size_t)row * Ktot + c4);
        }
        #pragma unroll
        for (int i = 0; i < 2; i++) {           // 64 rows x 8 chunks = 512
            const int ch  = tid + i * 256;
            const int row = ch >> 3;
            const int c4  = (ch & 7) << 2;
            cpa16(Bb + row * GPAD2 + c4, Wb + (size_t)row * CI + c4);
        }
        asm volatile("cp.async.commit_group;");
    };

    float acc[2][4][4];
    #pragma unroll
    for (int mt = 0; mt < 2; mt++)
        #pragma unroll
        for (int nt = 0; nt < 4; nt++)
            #pragma unroll
            for (int i = 0; i < 4; i++) acc[mt][nt][i] = 0.0f;

    load_tile(0, 0);
    for (int it = 0; it < NIT; it++) {
        if (it + 1 < NIT) {
            load_tile((it + 1) & 1, (it + 1) * BK);
            asm volatile("cp.async.wait_group 1;");
        } else {
            asm volatile("cp.async.wait_group 0;");
        }
        __syncthreads();
        const float* Ab = As + (it & 1) * 128 * GPAD2;
        const float* Bb = Bs + (it & 1) * 64 * GPAD2;
        #pragma unroll
        for (int ks = 0; ks < 4; ks++) {
            const int kb = ks * 8;
            uint32_t a[2][4], b[4][2];
            #pragma unroll
            for (int mt = 0; mt < 2; mt++) {
                ldsm4(a[mt][0], a[mt][1], a[mt][2], a[mt][3],
                      Ab + (warp_m * 32 + mt * 16 + a_lrow) * GPAD2 + kb + a_lcol);
                #pragma unroll
                for (int e = 0; e < 4; e++) a[mt][e] = u2tf32(a[mt][e]);
            }
            #pragma unroll
            for (int np = 0; np < 2; np++) {
                uint32_t r0, r1, r2, r3;
                ldsm4(r0, r1, r2, r3,
                      Bb + (warp_n * 32 + np * 16 + b_lrow) * GPAD2 + kb + b_lcol);
                b[np * 2    ][0] = u2tf32(r0);
                b[np * 2    ][1] = u2tf32(r1);
                b[np * 2 + 1][0] = u2tf32(r2);
                b[np * 2 + 1][1] = u2tf32(r3);
            }
            #pragma unroll
            for (int mt = 0; mt < 2; mt++)
                #pragma unroll
                for (int nt = 0; nt < 4; nt++)
                    mma_tf32(acc[mt][nt], a[mt], b[nt][0], b[nt][1]);
        }
        __syncthreads();
    }

    // ---- fused epilogue: this warp's 32 cols = head (go, h) ----
    const int h  = (o0 >> 5) + warp_n;
    const int gh = go * H + h;

    if (prob == 2) {
        // V: fp16, [b][gh][n][32]
        #pragma unroll
        for (int mt = 0; mt < 2; mt++)
            #pragma unroll
            for (int rh = 0; rh < 2; rh++) {
                const int row = t0 + warp_m * 32 + mt * 16 + grp + rh * 8;
                const int bb = row >> 9, n = row & 511;
                const size_t rb = (((size_t)bb * GH + gh) * SEQ + n) * 32;
                #pragma unroll
                for (int nt = 0; nt < 4; nt++) {
                    const int d0 = nt * 8 + 2 * qd;
                    half2 hv = __floats2half2_rn(acc[mt][nt][2 * rh],
                                                 acc[mt][nt][2 * rh + 1]);
                    *(half2*)&g_vh[rb + d0] = hv;
                }
            }
        return;
    }

    const float* wt = (prob == 0) ? qnw : knw;
    float invf[4], fr0[4], fr1[4], fr2[4], w1[4], w2[4];
    #pragma unroll
    for (int nt = 0; nt < 4; nt++) {
        const int f = nt * 4 + qd;
        invf[nt] = __expf(-(float)f * LOG1E4_OV16);
        const float* fp = pfreqs + (h * 16 + f) * 3;
        fr0[nt] = fp[0];  fr1[nt] = fp[1];  fr2[nt] = fp[2];
        const int d0 = nt * 8 + 2 * qd;
        w1[nt] = wt[d0];  w2[nt] = wt[d0 + 1];
    }
    float sg, cg;
    __sincosf(6.283185307179586f * (float)go * (1.0f / 12.0f), &sg, &cg);

    #pragma unroll
    for (int mt = 0; mt < 2; mt++)
        #pragma unroll
        for (int rh = 0; rh < 2; rh++) {
            // rms over head (32 dims): 8 local + qd-lane reduction
            float ss = 0.0f;
            #pragma unroll
            for (int nt = 0; nt < 4; nt++) {
                float v1 = acc[mt][nt][2 * rh], v2 = acc[mt][nt][2 * rh + 1];
                ss += v1 * v1 + v2 * v2;
            }
            ss += __shfl_xor_sync(0xffffffffu, ss, 1);
            ss += __shfl_xor_sync(0xffffffffu, ss, 2);
            const float rn = rsqrtf(ss * (1.0f / 32.0f) + EPS);

            const int row = t0 + warp_m * 32 + mt * 16 + grp + rh * 8;
            const int bb = row >> 9, n = row & 511;
            const float pos = (float)seq_idx[row];
            const float cx = coords[row * 3 + 0];
            const float cy = coords[row * 3 + 1];
            const float cz = coords[row * 3 + 2];
            const float c0 =  cx * cg + cy * sg;
            const float c1 = -cx * sg + cy * cg;
            const size_t rb = (((size_t)bb * GH + gh) * SEQ + n) * 32;

            #pragma unroll
            for (int nt = 0; nt < 4; nt++) {
                const float v1 = acc[mt][nt][2 * rh] * rn * w1[nt];
                const float v2 = acc[mt][nt][2 * rh + 1] * rn * w2[nt];
                const float ang = pos * invf[nt]
                                + c0 * fr0[nt] + c1 * fr1[nt] + cz * fr2[nt];
                float s, c;  sincosf(ang, &s, &c);
                const float o1 = v1 * c - v2 * s;
                const float o2 = v1 * s + v2 * c;
                const int d0 = nt * 8 + 2 * qd;
                if (prob == 0) {
                    *(float2*)&g_qT[rb + d0] = make_float2(o1, o2);
                } else {
                    uint32_t hi, lo;
                    pack_hilo(o1, o2, hi, lo);
                    *(uint32_t*)&g_khi[rb + d0] = hi;
                    *(uint32_t*)&g_klo[rb + d0] = lo;
                }
            }
        }
}

// ---------------- Wo GEMM (split-K=4, plain epilogue) -----------------------
__global__ void __launch_bounds__(256, 3) wo_gemm(const float* __restrict__ Wo)
{
    constexpr int CO = 64, CI = 256, BK = 32;
    constexpr int Ktot = DQK;              // 3072
    constexpr int Kper = Ktot / 4;         // 768
    constexpr int NIT  = Kper / BK;        // 24
    constexpr int Ntot = DOUT;             // 768

    extern __shared__ float sm[];
    float* As = sm;
    float* Bs = sm + 2 * 128 * GPAD2;

    const int ksl = blockIdx.z;
    const float* X = g_ao;
    float* Y = g_part + (size_t)ksl * T_TOK * Ntot;

    const int tid = threadIdx.x;
    const int n0 = blockIdx.x * 64;
    const int t0 = blockIdx.y * 128;
    const int go = n0 / CO;

    const int wid    = tid >> 5;
    const int lane   = tid & 31;
    const int warp_m = wid & 3;
    const int warp_n = wid >> 2;
    const int grp    = lane >> 2;
    const int qd     = lane & 3;

    const int a_lrow = lane & 15;
    const int a_lcol = (lane >> 4) * 4;
    const int b_lrow = ((lane >> 4) << 3) + (lane & 7);
    const int b_lcol = ((lane >> 3) & 1) * 4;

    auto load_tile = [&](int buf, int kk) {
        const int gi = kk / CI;
        const int i0 = kk % CI;
        const int wg = (gi - go + G) % G;
        const float* Xb = X + (size_t)t0 * Ktot + kk;
        const float* Wb = Wo + ((size_t)wg * CO) * CI + i0;
        float* Ab = As + buf * 128 * GPAD2;
        float* Bb = Bs + buf * 64 * GPAD2;
        #pragma unroll
        for (int i = 0; i < 4; i++) {
            const int ch  = tid + i * 256;
            const int row = ch >> 3;
            const int c4  = (ch & 7) << 2;
            cpa16(Ab + row * GPAD2 + c4, Xb + (size_t)row * Ktot + c4);
        }
        #pragma unroll
        for (int i = 0; i < 2; i++) {
            const int ch  = tid + i * 256;
            const int row = ch >> 3;
            const int c4  = (ch & 7) << 2;
            cpa16(Bb + row * GPAD2 + c4, Wb + (size_t)row * CI + c4);
        }
        asm volatile("cp.async.commit_group;");
    };

    float acc[2][4][4];
    #pragma unroll
    for (int mt = 0; mt < 2; mt++)
        #pragma unroll
        for (int nt = 0; nt < 4; nt++)
            #pragma unroll
            for (int i = 0; i < 4; i++) acc[mt][nt][i] = 0.0f;

    const int kbeg = ksl * Kper;
    load_tile(0, kbeg);
    for (int it = 0; it < NIT; it++) {
        if (it + 1 < NIT) {
            load_tile((it + 1) & 1, kbeg + (it + 1) * BK);
            asm volatile("cp.async.wait_group 1;");
        } else {
            asm volatile("cp.async.wait_group 0;");
        }
        __syncthreads();
        const float* Ab = As + (it & 1) * 128 * GPAD2;
        const float* Bb = Bs + (it & 1) * 64 * GPAD2;
        #pragma unroll
        for (int ks = 0; ks < 4; ks++) {
            const int kb = ks * 8;
            uint32_t a[2][4], b[4][2];
            #pragma unroll
            for (int mt = 0; mt < 2; mt++) {
                ldsm4(a[mt][0], a[mt][1], a[mt][2], a[mt][3],
                      Ab + (warp_m * 32 + mt * 16 + a_lrow) * GPAD2 + kb + a_lcol);
                #pragma unroll
                for (int e = 0; e < 4; e++) a[mt][e] = u2tf32(a[mt][e]);
            }
            #pragma unroll
            for (int np = 0; np < 2; np++) {
                uint32_t r0, r1, r2, r3;
                ldsm4(r0, r1, r2, r3,
                      Bb + (warp_n * 32 + np * 16 + b_lrow) * GPAD2 + kb + b_lcol);
                b[np * 2    ][0] = u2tf32(r0);
                b[np * 2    ][1] = u2tf32(r1);
                b[np * 2 + 1][0] = u2tf32(r2);
                b[np * 2 + 1][1] = u2tf32(r3);
            }
            #pragma unroll
            for (int mt = 0; mt < 2; mt++)
                #pragma unroll
                for (int nt = 0; nt < 4; nt++)
                    mma_tf32(acc[mt][nt], a[mt], b[nt][0], b[nt][1]);
        }
        __syncthreads();
    }

    #pragma unroll
    for (int mt = 0; mt < 2; mt++) {
        const int trow = t0 + warp_m * 32 + mt * 16 + grp;
        #pragma unroll
        for (int nt = 0; nt < 4; nt++) {
            const int ncol = n0 + warp_n * 32 + nt * 8 + 2 * qd;
            *(float2*)&Y[(size_t)trow * Ntot + ncol] =
                make_float2(acc[mt][nt][0], acc[mt][nt][1]);
            *(float2*)&Y[(size_t)(trow + 8) * Ntot + ncol] =
                make_float2(acc[mt][nt][2], acc[mt][nt][3]);
        }
    }
}

// ---------------- split-K reduce -------------------------------------------
__global__ void __launch_bounds__(256) reduce4_kernel(float* __restrict__ out)
{
    const int i = blockIdx.x * 256 + threadIdx.x;
    const size_t S = (size_t)T_TOK * DOUT / 4;
    const float4* p = (const float4*)g_part;
    float4 a = p[i], b = p[i + S], c = p[i + 2 * S], d = p[i + 3 * S];
    float4 r;
    r.x = (a.x + b.x) + (c.x + d.x);
    r.y = (a.y + b.y) + (c.y + d.y);
    r.z = (a.z + b.z) + (c.z + d.z);
    r.w = (a.w + b.w) + (c.w + d.w);
    ((float4*)out)[i] = r;
}

// ---------------- attention: fp16 hi/lo QK^T + fp16 PV ----------------------
// K hi/lo fp16 and V fp16 arrive pre-converted; prologue is a pure copy.
#define KPH 40   // half row stride (80 B: 16B-aligned, ldsm conflict-free)
#define ATTN_SMEM (3 * 512 * KPH * 2)   // 122880 B

__global__ void __launch_bounds__(256) attn_mma_kernel()
{
    extern __shared__ __half sh_h[];
    __half* Khi = sh_h;                 // [512][KPH]
    __half* Klo = sh_h + 512 * KPH;
    __half* Vs  = sh_h + 2 * 512 * KPH;

    const int qc = blockIdx.x;
    const int gh = blockIdx.y;
    const int b  = blockIdx.z;
    const int tid  = threadIdx.x;
    const int wid  = tid >> 5;
    const int lane = tid & 31;
    const int grp  = lane >> 2;
    const int qd   = lane & 3;

    const size_t base = ((size_t)b * GH + gh) * SEQ * 32;

    // ---- prologue: pure cp.async copy ----
    #pragma unroll
    for (int i = 0; i < 8; i++) {
        const int ch  = tid + i * 256;
        const int row = ch >> 2;
        const int c   = (ch & 3) * 8;
        cpa16(Khi + row * KPH + c, g_khi + base + row * 32 + c);
        cpa16(Klo + row * KPH + c, g_klo + base + row * 32 + c);
        cpa16(Vs  + row * KPH + c, g_vh  + base + row * 32 + c);
    }
    asm volatile("cp.async.commit_group;");

    // ---- Q fragments (fp16 hi/lo, scale folded), overlaps the copy ----
    const int qrow0 = qc * 256 + wid * 32;
    const float scale = 0.17677669529663687f;   // 1/sqrt(32)
    uint32_t qhi[2][2][4], qlo[2][2][4];
    #pragma unroll
    for (int mt = 0; mt < 2; mt++)
        #pragma unroll
        for (int kh = 0; kh < 2; kh++)
            #pragma unroll
            for (int e = 0; e < 4; e++) {
                const int row = mt * 16 + grp + (e & 1) * 8;
                const int col = kh * 16 + 2 * qd + (e >> 1) * 8;
                const float* qp = g_qT + base + (size_t)(qrow0 + row) * 32 + col;
                pack_hilo(qp[0] * scale, qp[1] * scale, qhi[mt][kh][e], qlo[mt][kh][e]);
            }

    asm volatile("cp.async.wait_group 0;");
    __syncthreads();

    float mrow[2][2], lrow[2][2];
    float o[2][4][4];
    #pragma unroll
    for (int mt = 0; mt < 2; mt++)
        #pragma unroll
        for (int hh = 0; hh < 2; hh++) { mrow[mt][hh] = -1e30f; lrow[mt][hh] = 0.0f; }
    #pragma unroll
    for (int mt = 0; mt < 2; mt++)
        #pragma unroll
        for (int nt = 0; nt < 4; nt++)
            #pragma unroll
            for (int c = 0; c < 4; c++) o[mt][nt][c] = 0.0f;

    // ldsm lane pieces: K (non-trans) and V (trans)
    const int k_key = ((lane >> 4) & 1) * 8 + (lane & 7);
    const int k_dof = ((lane >> 3) & 1) * 8;
    const int v_key = ((lane >> 3) & 1) * 8 + (lane & 7);
    const int v_dof = ((lane >> 4) & 1) * 8;

    float s[2][8][4];

    for (int kt = 0; kt < 8; kt++) {        // 8 key tiles of 64
        #pragma unroll
        for (int mt = 0; mt < 2; mt++)
            #pragma unroll
            for (int nt = 0; nt < 8; nt++)
                #pragma unroll
                for (int c = 0; c < 4; c++) s[mt][nt][c] = 0.0f;

        // ---- QK^T: fp16 hi/lo, 3 terms, K=16 per mma ----
        #pragma unroll
        for (int kh = 0; kh < 2; kh++) {
            const int dh = kh * 16;
            #pragma unroll
            for (int jp = 0; jp < 4; jp++) {
                const int kb = kt * 64 + jp * 16;
                uint32_t h0, h1, h2, h3, l0, l1, l2, l3;
                ldsm4(h0, h1, h2, h3, Khi + (kb + k_key) * KPH + dh + k_dof);
                ldsm4(l0, l1, l2, l3, Klo + (kb + k_key) * KPH + dh + k_dof);
                #pragma unroll
                for (int mt = 0; mt < 2; mt++) {
                    mma_f16(s[mt][jp * 2    ], qhi[mt][kh], h0, h1);
                    mma_f16(s[mt][jp * 2    ], qhi[mt][kh], l0, l1);
                    mma_f16(s[mt][jp * 2    ], qlo[mt][kh], h0, h1);
                    mma_f16(s[mt][jp * 2 + 1], qhi[mt][kh], h2, h3);
                    mma_f16(s[mt][jp * 2 + 1], qhi[mt][kh], l2, l3);
                    mma_f16(s[mt][jp * 2 + 1], qlo[mt][kh], h2, h3);
                }
            }
        }

        // ---- online softmax ----
        float esc[2][2];
        #pragma unroll
        for (int mt = 0; mt < 2; mt++)
            #pragma unroll
            for (int hh = 0; hh < 2; hh++) {
                float mx = -1e30f;
                #pragma unroll
                for (int nt = 0; nt < 8; nt++)
                    mx = fmaxf(mx, fmaxf(s[mt][nt][2 * hh], s[mt][nt][2 * hh + 1]));
                mx = fmaxf(mx, __shfl_xor_sync(0xffffffffu, mx, 1));
                mx = fmaxf(mx, __shfl_xor_sync(0xffffffffu, mx, 2));
                const float mnew = fmaxf(mrow[mt][hh], mx);
                esc[mt][hh] = __expf(mrow[mt][hh] - mnew);
                mrow[mt][hh] = mnew;
            }
        #pragma unroll
        for (int mt = 0; mt < 2; mt++)
            #pragma unroll
            for (int nt = 0; nt < 8; nt++)
                #pragma unroll
                for (int c = 0; c < 4; c++)
                    s[mt][nt][c] = __expf(s[mt][nt][c] - mrow[mt][c >> 1]);
        #pragma unroll
        for (int mt = 0; mt < 2; mt++)
            #pragma unroll
            for (int hh = 0; hh < 2; hh++) {
                float ps = 0.0f;
                #pragma unroll
                for (int nt = 0; nt < 8; nt++)
                    ps += s[mt][nt][2 * hh] + s[mt][nt][2 * hh + 1];
                ps += __shfl_xor_sync(0xffffffffu, ps, 1);
                ps += __shfl_xor_sync(0xffffffffu, ps, 2);
                lrow[mt][hh] = lrow[mt][hh] * esc[mt][hh] + ps;
            }
        #pragma unroll
        for (int mt = 0; mt < 2; mt++)
            #pragma unroll
            for (int nt = 0; nt < 4; nt++)
                #pragma unroll
                for (int c = 0; c < 4; c++)
                    o[mt][nt][c] *= esc[mt][c >> 1];

        // ---- P·V: fp16 m16n8k16, V frags via ldmatrix.trans ----
        #pragma unroll
        for (int j = 0; j < 4; j++) {       // 16-key sub-blocks
            const int kb = kt * 64 + j * 16;
            uint32_t vb[4][2];
            #pragma unroll
            for (int dv = 0; dv < 2; dv++) {
                uint32_t r0, r1, r2, r3;
                ldsm4t(r0, r1, r2, r3, Vs + (kb + v_key) * KPH + dv * 16 + v_dof);
                vb[dv * 2    ][0] = r0;  vb[dv * 2    ][1] = r1;
                vb[dv * 2 + 1][0] = r2;  vb[dv * 2 + 1][1] = r3;
            }
            #pragma unroll
            for (int mt = 0; mt < 2; mt++) {
                uint32_t ah[4], al[4];
                pack_hilo(s[mt][2*j  ][0], s[mt][2*j  ][1], ah[0], al[0]);
                pack_hilo(s[mt][2*j  ][2], s[mt][2*j  ][3], ah[1], al[1]);
                pack_hilo(s[mt][2*j+1][0], s[mt][2*j+1][1], ah[2], al[2]);
                pack_hilo(s[mt][2*j+1][2], s[mt][2*j+1][3], ah[3], al[3]);
                #pragma unroll
                for (int nt = 0; nt < 4; nt++) {
                    mma_f16(o[mt][nt], ah, vb[nt][0], vb[nt][1]);
                    mma_f16(o[mt][nt], al, vb[nt][0], vb[nt][1]);
                }
            }
        }
    }

    // ---- epilogue ----
    #pragma unroll
    for (int mt = 0; mt < 2; mt++) {
        const float inv0 = 1.0f / lrow[mt][0];
        const float inv1 = 1.0f / lrow[mt][1];
        const int n0 = qrow0 + mt * 16 + grp;
        #pragma unroll
        for (int nt = 0; nt < 4; nt++) {
            const int gcol = gh * 32 + nt * 8 + 2 * qd;
            *(float2*)&g_ao[((size_t)(b * SEQ + n0)) * DQK + gcol] =
                make_float2(o[mt][nt][0] * inv0, o[mt][nt][1] * inv0);
            *(float2*)&g_ao[((size_t)(b * SEQ + n0 + 8)) * DQK + gcol] =
                make_float2(o[mt][nt][2] * inv1, o[mt][nt][3] * inv1);
        }
    }
}

// ---------------- launch ---------------------------------------------------
extern "C" void kernel_launch(void* const* d_in, const int* in_sizes, int n_in,
                              void* d_out, int out_size)
{
    const float* feat   = (const float*)d_in[0];
    const float* coords = (const float*)d_in[1];
    const float* Wq     = (const float*)d_in[2];
    const float* Wk     = (const float*)d_in[3];
    const float* Wv     = (const float*)d_in[4];
    const float* Wo     = (const float*)d_in[5];
    const float* qnw    = (const float*)d_in[6];
    const float* knw    = (const float*)d_in[7];
    const float* pfrq   = (const float*)d_in[8];
    const int*   sidx   = (const int*)d_in[9];
    float* out = (float*)d_out;

    cudaFuncSetAttribute(qkv_gemm,
                         cudaFuncAttributeMaxDynamicSharedMemorySize, GEMM_SMEM);
    cudaFuncSetAttribute(wo_gemm,
                         cudaFuncAttributeMaxDynamicSharedMemorySize, GEMM_SMEM);
    cudaFuncSetAttribute(attn_mma_kernel,
                         cudaFuncAttributeMaxDynamicSharedMemorySize, ATTN_SMEM);

    // QKV projections with fused rms_norm + ropes + layout conversion
    qkv_gemm<<<dim3(DQK / 64, T_TOK / 128, 3), 256, GEMM_SMEM>>>(
        feat, Wq, Wk, Wv, coords, sidx, qnw, knw, pfrq);

    // attention
    attn_mma_kernel<<<dim3(2, GH, BATCH), 256, ATTN_SMEM>>>();

    // output projection, split-K=4 + reduce
    wo_gemm<<<dim3(DOUT / 64, T_TOK / 128, 4), 256, GEMM_SMEM>>>(Wo);
    reduce4_kernel<<<T_TOK * DOUT / 4 / 256, 256>>>(out);
}

// round 12
// speedup vs baseline: 5.4615x; 1.0262x over previous
#include <cuda_runtime.h>
#include <cuda_fp16.h>
#include <math.h>
#include <stdint.h>

#define G    12
#define H    8
#define CQK  32
#define CVAL 32
#define CIN  64
#define COUT 64
#define BATCH 2
#define SEQ  512
#define T_TOK (BATCH*SEQ)   // 1024 tokens
#define DIN  (G*CIN)        // 768
#define DQK  (G*H*CQK)      // 3072
#define GH   (G*H)          // 96
#define DOUT (G*COUT)       // 768

// ---------------- scratch (device globals; no allocation allowed) ----------
__device__ float  g_qT [T_TOK*DQK];                    // [b][gh][n][32] fp32
__device__ __align__(16) __half g_khi[T_TOK*DQK];      // [b][gh][n][32] fp16 hi
__device__ __align__(16) __half g_klo[T_TOK*DQK];      // fp16 lo residual
__device__ __align__(16) __half g_vh [T_TOK*DQK];      // [b][gh][n][32] fp16
__device__ float  g_ao [T_TOK*DQK];                    // attention out (tf32-rounded)
__device__ float  g_part[4*T_TOK*DOUT];                // Wo split-K partials
// tf32-prerounded inputs
__device__ float  g_xr [T_TOK*DIN];
__device__ float  g_wq [G*256*CIN];
__device__ float  g_wk [G*256*CIN];
__device__ float  g_wv [G*256*CIN];
__device__ float  g_wo [G*COUT*256];

__device__ __forceinline__ uint32_t f2tf32(float x) {
    uint32_t u;
    asm("cvt.rna.tf32.f32 %0, %1;" : "=r"(u) : "f"(x));
    return u;
}

__device__ __forceinline__ void mma_tf32(float* c, const uint32_t* a,
                                         uint32_t b0, uint32_t b1) {
    asm volatile(
        "mma.sync.aligned.m16n8k8.row.col.f32.tf32.tf32.f32 "
        "{%0,%1,%2,%3}, {%4,%5,%6,%7}, {%8,%9}, {%0,%1,%2,%3};"
        : "+f"(c[0]), "+f"(c[1]), "+f"(c[2]), "+f"(c[3])
        : "r"(a[0]), "r"(a[1]), "r"(a[2]), "r"(a[3]), "r"(b0), "r"(b1));
}
__device__ __forceinline__ void mma_f16(float* c, const uint32_t* a,
                                        uint32_t b0, uint32_t b1) {
    asm volatile(
        "mma.sync.aligned.m16n8k16.row.col.f32.f16.f16.f32 "
        "{%0,%1,%2,%3}, {%4,%5,%6,%7}, {%8,%9}, {%0,%1,%2,%3};"
        : "+f"(c[0]), "+f"(c[1]), "+f"(c[2]), "+f"(c[3])
        : "r"(a[0]), "r"(a[1]), "r"(a[2]), "r"(a[3]), "r"(b0), "r"(b1));
}
__device__ __forceinline__ void ldsm4(uint32_t& r0, uint32_t& r1,
                                      uint32_t& r2, uint32_t& r3, const void* p) {
    uint32_t a = (uint32_t)__cvta_generic_to_shared(p);
    asm volatile("ldmatrix.sync.aligned.m8n8.x4.shared.b16 {%0,%1,%2,%3}, [%4];"
                 : "=r"(r0), "=r"(r1), "=r"(r2), "=r"(r3) : "r"(a));
}
__device__ __forceinline__ void ldsm4t(uint32_t& r0, uint32_t& r1,
                                       uint32_t& r2, uint32_t& r3, const void* p) {
    uint32_t a = (uint32_t)__cvta_generic_to_shared(p);
    asm volatile("ldmatrix.sync.aligned.m8n8.x4.trans.shared.b16 {%0,%1,%2,%3}, [%4];"
                 : "=r"(r0), "=r"(r1), "=r"(r2), "=r"(r3) : "r"(a));
}
__device__ __forceinline__ void cpa16(void* smem, const void* gmem) {
    uint32_t s = (uint32_t)__cvta_generic_to_shared(smem);
    asm volatile("cp.async.cg.shared.global [%0], [%1], 16;" :: "r"(s), "l"(gmem));
}
__device__ __forceinline__ uint32_t packh2(float a, float b) {
    half2 h = __floats2half2_rn(a, b);
    return *reinterpret_cast<uint32_t*>(&h);
}
__device__ __forceinline__ void pack_hilo(float a, float b,
                                          uint32_t& hi, uint32_t& lo) {
    half2 h = __floats2half2_rn(a, b);
    float2 hf = __half22float2(h);
    half2 l = __floats2half2_rn(a - hf.x, b - hf.y);
    hi = *reinterpret_cast<uint32_t*>(&h);
    lo = *reinterpret_cast<uint32_t*>(&l);
}

#define EPS 1.1920929e-07f
#define LOG1E4_OV16 (9.210340371976184f / 16.0f)

// ---------------- prep: round inputs to tf32 (rna) in fp32 containers -------
// regions (float4 units): X 196608 | Wq 49152 | Wk 49152 | Wv 49152 | Wo 49152
#define PREP_F4 393216
__global__ void __launch_bounds__(256) round_prep(
    const float* __restrict__ X,  const float* __restrict__ Wq,
    const float* __restrict__ Wk, const float* __restrict__ Wv,
    const float* __restrict__ Wo)
{
    const int i = blockIdx.x * 256 + threadIdx.x;
    const float* src;  float* dst;  int off;
    if      (i < 196608) { src = X;  dst = g_xr; off = i; }
    else if (i < 245760) { src = Wq; dst = g_wq; off = i - 196608; }
    else if (i < 294912) { src = Wk; dst = g_wk; off = i - 245760; }
    else if (i < 344064) { src = Wv; dst = g_wv; off = i - 294912; }
    else                 { src = Wo; dst = g_wo; off = i - 344064; }
    float4 v = ((const float4*)src)[off];
    v.x = __uint_as_float(f2tf32(v.x));
    v.y = __uint_as_float(f2tf32(v.y));
    v.z = __uint_as_float(f2tf32(v.z));
    v.w = __uint_as_float(f2tf32(v.w));
    ((float4*)dst)[off] = v;
}

// ---------------- QKV GEMM with fused rms_norm + ropes ----------------------
// BM=128 x BN=64 x BK=32, double-buffered cp.async, tf32 mma (inputs
// pre-rounded -> no in-loop cvt). z selects {Q,K,V}.
#define GPAD2 36
#define GEMM_SMEM ((2*128*GPAD2 + 2*64*GPAD2) * 4)   // 55296 B

__global__ void __launch_bounds__(256, 3) qkv_gemm(
    const float* __restrict__ coords, const int* __restrict__ seq_idx,
    const float* __restrict__ qnw, const float* __restrict__ knw,
    const float* __restrict__ pfreqs)
{
    constexpr int CO = 256, CI = 64, BK = 32;
    constexpr int Ktot = G * CI;       // 768
    constexpr int NIT  = Ktot / BK;    // 24

    extern __shared__ float sm[];
    float* As = sm;                      // [2][128][GPAD2]
    float* Bs = sm + 2 * 128 * GPAD2;    // [2][64][GPAD2]

    const int prob = blockIdx.z;
    const float* X = g_xr;
    const float* W = (prob == 0) ? g_wq : (prob == 1) ? g_wk : g_wv;

    const int tid = threadIdx.x;
    const int n0 = blockIdx.x * 64;
    const int t0 = blockIdx.y * 128;
    const int go = n0 / CO;
    const int o0 = n0 % CO;

    const int wid    = tid >> 5;
    const int lane   = tid & 31;
    const int warp_m = wid & 3;
    const int warp_n = wid >> 2;
    const int grp    = lane >> 2;
    const int qd     = lane & 3;

    const int a_lrow = lane & 15;
    const int a_lcol = (lane >> 4) * 4;
    const int b_lrow = ((lane >> 4) << 3) + (lane & 7);
    const int b_lcol = ((lane >> 3) & 1) * 4;

    auto load_tile = [&](int buf, int kk) {
        const int gi = kk / CI;
        const int i0 = kk % CI;
        const int wg = (gi - go + G) % G;
        const float* Xb = X + (size_t)t0 * Ktot + kk;
        const float* Wb = W + ((size_t)wg * CO + o0) * CI + i0;
        float* Ab = As + buf * 128 * GPAD2;
        float* Bb = Bs + buf * 64 * GPAD2;
        #pragma unroll
        for (int i = 0; i < 4; i++) {
            const int ch  = tid + i * 256;
            const int row = ch >> 3;
            const int c4  = (ch & 7) << 2;
            cpa16(Ab + row * GPAD2 + c4, Xb + (size_t)row * Ktot + c4);
        }
        #pragma unroll
        for (int i = 0; i < 2; i++) {
            const int ch  = tid + i * 256;
            const int row = ch >> 3;
            const int c4  = (ch & 7) << 2;
            cpa16(Bb + row * GPAD2 + c4, Wb + (size_t)row * CI + c4);
        }
        asm volatile("cp.async.commit_group;");
    };

    float acc[2][4][4];
    #pragma unroll
    for (int mt = 0; mt < 2; mt++)
        #pragma unroll
        for (int nt = 0; nt < 4; nt++)
            #pragma unroll
            for (int i = 0; i < 4; i++) acc[mt][nt][i] = 0.0f;

    load_tile(0, 0);
    for (int it = 0; it < NIT; it++) {
        if (it + 1 < NIT) {
            load_tile((it + 1) & 1, (it + 1) * BK);
            asm volatile("cp.async.wait_group 1;");
        } else {
            asm volatile("cp.async.wait_group 0;");
        }
        __syncthreads();
        const float* Ab = As + (it & 1) * 128 * GPAD2;
        const float* Bb = Bs + (it & 1) * 64 * GPAD2;
        #pragma unroll
        for (int ks = 0; ks < 4; ks++) {
            const int kb = ks * 8;
            uint32_t a[2][4], b[4][2];
            #pragma unroll
            for (int mt = 0; mt < 2; mt++)
                ldsm4(a[mt][0], a[mt][1], a[mt][2], a[mt][3],
                      Ab + (warp_m * 32 + mt * 16 + a_lrow) * GPAD2 + kb + a_lcol);
            #pragma unroll
            for (int np = 0; np < 2; np++) {
                uint32_t r0, r1, r2, r3;
                ldsm4(r0, r1, r2, r3,
                      Bb + (warp_n * 32 + np * 16 + b_lrow) * GPAD2 + kb + b_lcol);
                b[np * 2    ][0] = r0;  b[np * 2    ][1] = r1;
                b[np * 2 + 1][0] = r2;  b[np * 2 + 1][1] = r3;
            }
            #pragma unroll
            for (int mt = 0; mt < 2; mt++)
                #pragma unroll
                for (int nt = 0; nt < 4; nt++)
                    mma_tf32(acc[mt][nt], a[mt], b[nt][0], b[nt][1]);
        }
        __syncthreads();
    }

    // ---- fused epilogue: this warp's 32 cols = head (go, h) ----
    const int h  = (o0 >> 5) + warp_n;
    const int gh = go * H + h;

    if (prob == 2) {
        #pragma unroll
        for (int mt = 0; mt < 2; mt++)
            #pragma unroll
            for (int rh = 0; rh < 2; rh++) {
                const int row = t0 + warp_m * 32 + mt * 16 + grp + rh * 8;
                const int bb = row >> 9, n = row & 511;
                const size_t rb = (((size_t)bb * GH + gh) * SEQ + n) * 32;
                #pragma unroll
                for (int nt = 0; nt < 4; nt++) {
                    const int d0 = nt * 8 + 2 * qd;
                    half2 hv = __floats2half2_rn(acc[mt][nt][2 * rh],
                                                 acc[mt][nt][2 * rh + 1]);
                    *(half2*)&g_vh[rb + d0] = hv;
                }
            }
        return;
    }

    const float* wt = (prob == 0) ? qnw : knw;
    float invf[4], fr0[4], fr1[4], fr2[4], w1[4], w2[4];
    #pragma unroll
    for (int nt = 0; nt < 4; nt++) {
        const int f = nt * 4 + qd;
        invf[nt] = __expf(-(float)f * LOG1E4_OV16);
        const float* fp = pfreqs + (h * 16 + f) * 3;
        fr0[nt] = fp[0];  fr1[nt] = fp[1];  fr2[nt] = fp[2];
        const int d0 = nt * 8 + 2 * qd;
        w1[nt] = wt[d0];  w2[nt] = wt[d0 + 1];
    }
    float sg, cg;
    __sincosf(6.283185307179586f * (float)go * (1.0f / 12.0f), &sg, &cg);

    #pragma unroll
    for (int mt = 0; mt < 2; mt++)
        #pragma unroll
        for (int rh = 0; rh < 2; rh++) {
            float ss = 0.0f;
            #pragma unroll
            for (int nt = 0; nt < 4; nt++) {
                float v1 = acc[mt][nt][2 * rh], v2 = acc[mt][nt][2 * rh + 1];
                ss += v1 * v1 + v2 * v2;
            }
            ss += __shfl_xor_sync(0xffffffffu, ss, 1);
            ss += __shfl_xor_sync(0xffffffffu, ss, 2);
            const float rn = rsqrtf(ss * (1.0f / 32.0f) + EPS);

            const int row = t0 + warp_m * 32 + mt * 16 + grp + rh * 8;
            const int bb = row >> 9, n = row & 511;
            const float pos = (float)seq_idx[row];
            const float cx = coords[row * 3 + 0];
            const float cy = coords[row * 3 + 1];
            const float cz = coords[row * 3 + 2];
            const float c0 =  cx * cg + cy * sg;
            const float c1 = -cx * sg + cy * cg;
            const size_t rb = (((size_t)bb * GH + gh) * SEQ + n) * 32;

            #pragma unroll
            for (int nt = 0; nt < 4; nt++) {
                const float v1 = acc[mt][nt][2 * rh] * rn * w1[nt];
                const float v2 = acc[mt][nt][2 * rh + 1] * rn * w2[nt];
                const float ang = pos * invf[nt]
                                + c0 * fr0[nt] + c1 * fr1[nt] + cz * fr2[nt];
                float s, c;  sincosf(ang, &s, &c);
                const float o1 = v1 * c - v2 * s;
                const float o2 = v1 * s + v2 * c;
                const int d0 = nt * 8 + 2 * qd;
                if (prob == 0) {
                    *(float2*)&g_qT[rb + d0] = make_float2(o1, o2);
                } else {
                    uint32_t hi, lo;
                    pack_hilo(o1, o2, hi, lo);
                    *(uint32_t*)&g_khi[rb + d0] = hi;
                    *(uint32_t*)&g_klo[rb + d0] = lo;
                }
            }
        }
}

// ---------------- Wo GEMM (split-K=4, inputs pre-rounded) -------------------
__global__ void __launch_bounds__(256, 3) wo_gemm()
{
    constexpr int CO = 64, CI = 256, BK = 32;
    constexpr int Ktot = DQK;              // 3072
    constexpr int Kper = Ktot / 4;         // 768
    constexpr int NIT  = Kper / BK;        // 24
    constexpr int Ntot = DOUT;             // 768

    extern __shared__ float sm[];
    float* As = sm;
    float* Bs = sm + 2 * 128 * GPAD2;

    const int ksl = blockIdx.z;
    const float* X = g_ao;
    float* Y = g_part + (size_t)ksl * T_TOK * Ntot;

    const int tid = threadIdx.x;
    const int n0 = blockIdx.x * 64;
    const int t0 = blockIdx.y * 128;
    const int go = n0 / CO;

    const int wid    = tid >> 5;
    const int lane   = tid & 31;
    const int warp_m = wid & 3;
    const int warp_n = wid >> 2;
    const int grp    = lane >> 2;
    const int qd     = lane & 3;

    const int a_lrow = lane & 15;
    const int a_lcol = (lane >> 4) * 4;
    const int b_lrow = ((lane >> 4) << 3) + (lane & 7);
    const int b_lcol = ((lane >> 3) & 1) * 4;

    auto load_tile = [&](int buf, int kk) {
        const int gi = kk / CI;
        const int i0 = kk % CI;
        const int wg = (gi - go + G) % G;
        const float* Xb = X + (size_t)t0 * Ktot + kk;
        const float* Wb = g_wo + ((size_t)wg * CO) * CI + i0;
        float* Ab = As + buf * 128 * GPAD2;
        float* Bb = Bs + buf * 64 * GPAD2;
        #pragma unroll
        for (int i = 0; i < 4; i++) {
            const int ch  = tid + i * 256;
            const int row = ch >> 3;
            const int c4  = (ch & 7) << 2;
            cpa16(Ab + row * GPAD2 + c4, Xb + (size_t)row * Ktot + c4);
        }
        #pragma unroll
        for (int i = 0; i < 2; i++) {
            const int ch  = tid + i * 256;
            const int row = ch >> 3;
            const int c4  = (ch & 7) << 2;
            cpa16(Bb + row * GPAD2 + c4, Wb + (size_t)row * CI + c4);
        }
        asm volatile("cp.async.commit_group;");
    };

    float acc[2][4][4];
    #pragma unroll
    for (int mt = 0; mt < 2; mt++)
        #pragma unroll
        for (int nt = 0; nt < 4; nt++)
            #pragma unroll
            for (int i = 0; i < 4; i++) acc[mt][nt][i] = 0.0f;

    const int kbeg = ksl * Kper;
    load_tile(0, kbeg);
    for (int it = 0; it < NIT; it++) {
        if (it + 1 < NIT) {
            load_tile((it + 1) & 1, kbeg + (it + 1) * BK);
            asm volatile("cp.async.wait_group 1;");
        } else {
            asm volatile("cp.async.wait_group 0;");
        }
        __syncthreads();
        const float* Ab = As + (it & 1) * 128 * GPAD2;
        const float* Bb = Bs + (it & 1) * 64 * GPAD2;
        #pragma unroll
        for (int ks = 0; ks < 4; ks++) {
            const int kb = ks * 8;
            uint32_t a[2][4], b[4][2];
            #pragma unroll
            for (int mt = 0; mt < 2; mt++)
                ldsm4(a[mt][0], a[mt][1], a[mt][2], a[mt][3],
                      Ab + (warp_m * 32 + mt * 16 + a_lrow) * GPAD2 + kb + a_lcol);
            #pragma unroll
            for (int np = 0; np < 2; np++) {
                uint32_t r0, r1, r2, r3;
                ldsm4(r0, r1, r2, r3,
                      Bb + (warp_n * 32 + np * 16 + b_lrow) * GPAD2 + kb + b_lcol);
                b[np * 2    ][0] = r0;  b[np * 2    ][1] = r1;
                b[np * 2 + 1][0] = r2;  b[np * 2 + 1][1] = r3;
            }
            #pragma unroll
            for (int mt = 0; mt < 2; mt++)
                #pragma unroll
                for (int nt = 0; nt < 4; nt++)
                    mma_tf32(acc[mt][nt], a[mt], b[nt][0], b[nt][1]);
        }
        __syncthreads();
    }

    #pragma unroll
    for (int mt = 0; mt < 2; mt++) {
        const int trow = t0 + warp_m * 32 + mt * 16 + grp;
        #pragma unroll
        for (int nt = 0; nt < 4; nt++) {
            const int ncol = n0 + warp_n * 32 + nt * 8 + 2 * qd;
            *(float2*)&Y[(size_t)trow * Ntot + ncol] =
                make_float2(acc[mt][nt][0], acc[mt][nt][1]);
            *(float2*)&Y[(size_t)(trow + 8) * Ntot + ncol] =
                make_float2(acc[mt][nt][2], acc[mt][nt][3]);
        }
    }
}

// ---------------- split-K reduce -------------------------------------------
__global__ void __launch_bounds__(256) reduce4_kernel(float* __restrict__ out)
{
    const int i = blockIdx.x * 256 + threadIdx.x;
    const size_t S = (size_t)T_TOK * DOUT / 4;
    const float4* p = (const float4*)g_part;
    float4 a = p[i], b = p[i + S], c = p[i + 2 * S], d = p[i + 3 * S];
    float4 r;
    r.x = (a.x + b.x) + (c.x + d.x);
    r.y = (a.y + b.y) + (c.y + d.y);
    r.z = (a.z + b.z) + (c.z + d.z);
    r.w = (a.w + b.w) + (c.w + d.w);
    ((float4*)out)[i] = r;
}

// ---------------- attention: 512 threads, 16-query warps --------------------
// fp16 hi/lo QK^T (3-term) + fp16 PV (P hi only). ~90 regs/thread, 16 warps/SM.
#define KPH 40   // half row stride (80 B: 16B-aligned rows, ldsm conflict-free)
#define ATTN_SMEM (3 * 512 * KPH * 2)   // 122880 B

__global__ void __launch_bounds__(512) attn_mma_kernel()
{
    extern __shared__ __half sh_h[];
    __half* Khi = sh_h;                 // [512][KPH]
    __half* Klo = sh_h + 512 * KPH;
    __half* Vs  = sh_h + 2 * 512 * KPH;

    const int qc = blockIdx.x;   // 0..1
    const int gh = blockIdx.y;
    const int b  = blockIdx.z;
    const int tid  = threadIdx.x;
    const int wid  = tid >> 5;   // 0..15
    const int lane = tid & 31;
    const int grp  = lane >> 2;
    const int qd   = lane & 3;

    const size_t base = ((size_t)b * GH + gh) * SEQ * 32;

    // ---- prologue: pure cp.async copy ----
    #pragma unroll
    for (int i = 0; i < 4; i++) {
        const int ch  = tid + i * 512;
        const int row = ch >> 2;
        const int c   = (ch & 3) * 8;
        cpa16(Khi + row * KPH + c, g_khi + base + row * 32 + c);
        cpa16(Klo + row * KPH + c, g_klo + base + row * 32 + c);
        cpa16(Vs  + row * KPH + c, g_vh  + base + row * 32 + c);
    }
    asm volatile("cp.async.commit_group;");

    // ---- Q fragments (fp16 hi/lo, scale folded) ----
    const int qrow0 = qc * 256 + wid * 16;
    const float scale = 0.17677669529663687f;   // 1/sqrt(32)
    uint32_t qhi[2][4], qlo[2][4];
    #pragma unroll
    for (int kh = 0; kh < 2; kh++)
        #pragma unroll
        for (int e = 0; e < 4; e++) {
            const int row = grp + (e & 1) * 8;
            const int col = kh * 16 + 2 * qd + (e >> 1) * 8;
            const float* qp = g_qT + base + (size_t)(qrow0 + row) * 32 + col;
            pack_hilo(qp[0] * scale, qp[1] * scale, qhi[kh][e], qlo[kh][e]);
        }

    asm volatile("cp.async.wait_group 0;");
    __syncthreads();

    float mrow[2] = {-1e30f, -1e30f}, lrow[2] = {0.0f, 0.0f};
    float o[4][4];
    #pragma unroll
    for (int nt = 0; nt < 4; nt++)
        #pragma unroll
        for (int c = 0; c < 4; c++) o[nt][c] = 0.0f;

    const int k_key = ((lane >> 4) & 1) * 8 + (lane & 7);
    const int k_dof = ((lane >> 3) & 1) * 8;
    const int v_key = ((lane >> 3) & 1) * 8 + (lane & 7);
    const int v_dof = ((lane >> 4) & 1) * 8;

    float s[8][4];

    for (int kt = 0; kt < 8; kt++) {        // 8 key tiles of 64
        #pragma unroll
        for (int nt = 0; nt < 8; nt++)
            #pragma unroll
            for (int c = 0; c < 4; c++) s[nt][c] = 0.0f;

        // ---- QK^T: fp16 hi/lo 3-term ----
        #pragma unroll
        for (int kh = 0; kh < 2; kh++) {
            const int dh = kh * 16;
            #pragma unroll
            for (int jp = 0; jp < 4; jp++) {
                const int kb = kt * 64 + jp * 16;
                uint32_t h0, h1, h2, h3, l0, l1, l2, l3;
                ldsm4(h0, h1, h2, h3, Khi + (kb + k_key) * KPH + dh + k_dof);
                ldsm4(l0, l1, l2, l3, Klo + (kb + k_key) * KPH + dh + k_dof);
                mma_f16(s[jp * 2    ], qhi[kh], h0, h1);
                mma_f16(s[jp * 2    ], qhi[kh], l0, l1);
                mma_f16(s[jp * 2    ], qlo[kh], h0, h1);
                mma_f16(s[jp * 2 + 1], qhi[kh], h2, h3);
                mma_f16(s[jp * 2 + 1], qhi[kh], l2, l3);
                mma_f16(s[jp * 2 + 1], qlo[kh], h2, h3);
            }
        }

        // ---- online softmax ----
        float esc[2];
        #pragma unroll
        for (int hh = 0; hh < 2; hh++) {
            float mx = -1e30f;
            #pragma unroll
            for (int nt = 0; nt < 8; nt++)
                mx = fmaxf(mx, fmaxf(s[nt][2 * hh], s[nt][2 * hh + 1]));
            mx = fmaxf(mx, __shfl_xor_sync(0xffffffffu, mx, 1));
            mx = fmaxf(mx, __shfl_xor_sync(0xffffffffu, mx, 2));
            const float mnew = fmaxf(mrow[hh], mx);
            esc[hh] = __expf(mrow[hh] - mnew);
            mrow[hh] = mnew;
        }
        #pragma unroll
        for (int nt = 0; nt < 8; nt++)
            #pragma unroll
            for (int c = 0; c < 4; c++)
                s[nt][c] = __expf(s[nt][c] - mrow[c >> 1]);
        #pragma unroll
        for (int hh = 0; hh < 2; hh++) {
            float ps = 0.0f;
            #pragma unroll
            for (int nt = 0; nt < 8; nt++)
                ps += s[nt][2 * hh] + s[nt][2 * hh + 1];
            ps += __shfl_xor_sync(0xffffffffu, ps, 1);
            ps += __shfl_xor_sync(0xffffffffu, ps, 2);
            lrow[hh] = lrow[hh] * esc[hh] + ps;
        }
        #pragma unroll
        for (int nt = 0; nt < 4; nt++)
            #pragma unroll
            for (int c = 0; c < 4; c++)
                o[nt][c] *= esc[c >> 1];

        // ---- P·V: fp16 m16n8k16, P hi only, V frags via ldmatrix.trans ----
        #pragma unroll
        for (int j = 0; j < 4; j++) {
            const int kb = kt * 64 + j * 16;
            uint32_t vb[4][2];
            #pragma unroll
            for (int dv = 0; dv < 2; dv++) {
                uint32_t r0, r1, r2, r3;
                ldsm4t(r0, r1, r2, r3, Vs + (kb + v_key) * KPH + dv * 16 + v_dof);
                vb[dv * 2    ][0] = r0;  vb[dv * 2    ][1] = r1;
                vb[dv * 2 + 1][0] = r2;  vb[dv * 2 + 1][1] = r3;
            }
            uint32_t ah[4];
            ah[0] = packh2(s[2*j  ][0], s[2*j  ][1]);
            ah[1] = packh2(s[2*j  ][2], s[2*j  ][3]);
            ah[2] = packh2(s[2*j+1][0], s[2*j+1][1]);
            ah[3] = packh2(s[2*j+1][2], s[2*j+1][3]);
            #pragma unroll
            for (int nt = 0; nt < 4; nt++)
                mma_f16(o[nt], ah, vb[nt][0], vb[nt][1]);
        }
    }

    // ---- epilogue (tf32-round g_ao for the Wo GEMM) ----
    const float inv0 = 1.0f / lrow[0];
    const float inv1 = 1.0f / lrow[1];
    const int n0 = qrow0 + grp;
    #pragma unroll
    for (int nt = 0; nt < 4; nt++) {
        const int gcol = gh * 32 + nt * 8 + 2 * qd;
        *(float2*)&g_ao[((size_t)(b * SEQ + n0)) * DQK + gcol] = make_float2(
            __uint_as_float(f2tf32(o[nt][0] * inv0)),
            __uint_as_float(f2tf32(o[nt][1] * inv0)));
        *(float2*)&g_ao[((size_t)(b * SEQ + n0 + 8)) * DQK + gcol] = make_float2(
            __uint_as_float(f2tf32(o[nt][2] * inv1)),
            __uint_as_float(f2tf32(o[nt][3] * inv1)));
    }
}

// ---------------- launch ---------------------------------------------------
extern "C" void kernel_launch(void* const* d_in, const int* in_sizes, int n_in,
                              void* d_out, int out_size)
{
    const float* feat   = (const float*)d_in[0];
    const float* coords = (const float*)d_in[1];
    const float* Wq     = (const float*)d_in[2];
    const float* Wk     = (const float*)d_in[3];
    const float* Wv     = (const float*)d_in[4];
    const float* Wo     = (const float*)d_in[5];
    const float* qnw    = (const float*)d_in[6];
    const float* knw    = (const float*)d_in[7];
    const float* pfrq   = (const float*)d_in[8];
    const int*   sidx   = (const int*)d_in[9];
    float* out = (float*)d_out;

    cudaFuncSetAttribute(qkv_gemm,
                         cudaFuncAttributeMaxDynamicSharedMemorySize, GEMM_SMEM);
    cudaFuncSetAttribute(wo_gemm,
                         cudaFuncAttributeMaxDynamicSharedMemorySize, GEMM_SMEM);
    cudaFuncSetAttribute(attn_mma_kernel,
                         cudaFuncAttributeMaxDynamicSharedMemorySize, ATTN_SMEM);

    // pre-round inputs to tf32
    round_prep<<<PREP_F4 / 256, 256>>>(feat, Wq, Wk, Wv, Wo);

    // QKV projections with fused rms_norm + ropes + layout conversion
    qkv_gemm<<<dim3(DQK / 64, T_TOK / 128, 3), 256, GEMM_SMEM>>>(
        coords, sidx, qnw, knw, pfrq);

    // attention
    attn_mma_kernel<<<dim3(2, GH, BATCH), 512, ATTN_SMEM>>>();

    // output projection, split-K=4 + reduce
    wo_gemm<<<dim3(DOUT / 64, T_TOK / 128, 4), 256, GEMM_SMEM>>>();
    reduce4_kernel<<<T_TOK * DOUT / 4 / 256, 256>>>(out);
}

// round 13
// speedup vs baseline: 8.4306x; 1.5436x over previous
#include <cuda_runtime.h>
#include <cuda_fp16.h>
#include <math.h>
#include <stdint.h>

#define G    12
#define H    8
#define CQK  32
#define CVAL 32
#define CIN  64
#define COUT 64
#define BATCH 2
#define SEQ  512
#define T_TOK (BATCH*SEQ)   // 1024 tokens
#define DIN  (G*CIN)        // 768
#define DQK  (G*H*CQK)      // 3072
#define GH   (G*H)          // 96
#define DOUT (G*COUT)       // 768

// ---------------- scratch (device globals; no allocation allowed) ----------
__device__ float  g_qT [T_TOK*DQK];                    // [b][gh][n][32] fp32
__device__ __align__(16) __half g_khi[T_TOK*DQK];      // [b][gh][n][32] fp16 hi
__device__ __align__(16) __half g_klo[T_TOK*DQK];      // fp16 lo residual
__device__ __align__(16) __half g_vh [T_TOK*DQK];      // [b][gh][n][32] fp16
__device__ __align__(16) __half g_aoh[T_TOK*DQK];      // attention out fp16
__device__ float  g_part[4*T_TOK*DOUT];                // Wo split-K partials
// fp16-converted inputs
__device__ __align__(16) __half g_xh [T_TOK*DIN];
__device__ __align__(16) __half g_wqh[G*256*CIN];
__device__ __align__(16) __half g_wkh[G*256*CIN];
__device__ __align__(16) __half g_wvh[G*256*CIN];
__device__ __align__(16) __half g_woh[G*COUT*256];

__device__ __forceinline__ void mma_f16(float* c, const uint32_t* a,
                                        uint32_t b0, uint32_t b1) {
    asm volatile(
        "mma.sync.aligned.m16n8k16.row.col.f32.f16.f16.f32 "
        "{%0,%1,%2,%3}, {%4,%5,%6,%7}, {%8,%9}, {%0,%1,%2,%3};"
        : "+f"(c[0]), "+f"(c[1]), "+f"(c[2]), "+f"(c[3])
        : "r"(a[0]), "r"(a[1]), "r"(a[2]), "r"(a[3]), "r"(b0), "r"(b1));
}
__device__ __forceinline__ void ldsm4(uint32_t& r0, uint32_t& r1,
                                      uint32_t& r2, uint32_t& r3, const void* p) {
    uint32_t a = (uint32_t)__cvta_generic_to_shared(p);
    asm volatile("ldmatrix.sync.aligned.m8n8.x4.shared.b16 {%0,%1,%2,%3}, [%4];"
                 : "=r"(r0), "=r"(r1), "=r"(r2), "=r"(r3) : "r"(a));
}
__device__ __forceinline__ void ldsm4t(uint32_t& r0, uint32_t& r1,
                                       uint32_t& r2, uint32_t& r3, const void* p) {
    uint32_t a = (uint32_t)__cvta_generic_to_shared(p);
    asm volatile("ldmatrix.sync.aligned.m8n8.x4.trans.shared.b16 {%0,%1,%2,%3}, [%4];"
                 : "=r"(r0), "=r"(r1), "=r"(r2), "=r"(r3) : "r"(a));
}
__device__ __forceinline__ void cpa16(void* smem, const void* gmem) {
    uint32_t s = (uint32_t)__cvta_generic_to_shared(smem);
    asm volatile("cp.async.cg.shared.global [%0], [%1], 16;" :: "r"(s), "l"(gmem));
}
__device__ __forceinline__ uint32_t packh2(float a, float b) {
    half2 h = __floats2half2_rn(a, b);
    return *reinterpret_cast<uint32_t*>(&h);
}
__device__ __forceinline__ void pack_hilo(float a, float b,
                                          uint32_t& hi, uint32_t& lo) {
    half2 h = __floats2half2_rn(a, b);
    float2 hf = __half22float2(h);
    half2 l = __floats2half2_rn(a - hf.x, b - hf.y);
    hi = *reinterpret_cast<uint32_t*>(&h);
    lo = *reinterpret_cast<uint32_t*>(&l);
}

#define EPS 1.1920929e-07f
#define LOG1E4_OV16 (9.210340371976184f / 16.0f)

// ---------------- prep: convert inputs to fp16 ------------------------------
// regions (8-float units): X 98304 | Wq 24576 | Wk 24576 | Wv 24576 | Wo 24576
#define PREP_T 196608
__global__ void __launch_bounds__(256) half_prep(
    const float* __restrict__ X,  const float* __restrict__ Wq,
    const float* __restrict__ Wk, const float* __restrict__ Wv,
    const float* __restrict__ Wo)
{
    const int i = blockIdx.x * 256 + threadIdx.x;
    const float* src;  __half* dst;  int off;
    if      (i <  98304) { src = X;  dst = g_xh;  off = i; }
    else if (i < 122880) { src = Wq; dst = g_wqh; off = i -  98304; }
    else if (i < 147456) { src = Wk; dst = g_wkh; off = i - 122880; }
    else if (i < 172032) { src = Wv; dst = g_wvh; off = i - 147456; }
    else                 { src = Wo; dst = g_woh; off = i - 172032; }
    float4 v0 = ((const float4*)src)[2 * off];
    float4 v1 = ((const float4*)src)[2 * off + 1];
    uint4 r;
    r.x = packh2(v0.x, v0.y);  r.y = packh2(v0.z, v0.w);
    r.z = packh2(v1.x, v1.y);  r.w = packh2(v1.z, v1.w);
    ((uint4*)dst)[off] = r;
}

// ---------------- QKV GEMM (fp16 m16n8k16) with fused rms_norm + ropes ------
// BM=128 x BN=64 x BK=64, double-buffered cp.async. z selects {Q,K,V}.
#define HPAD 72   // half row stride (144 B = 36 words; 36 mod 32 = 4 -> clean)
#define GEMM_SMEM ((2*128*HPAD + 2*64*HPAD) * 2)   // 55296 B

__global__ void __launch_bounds__(256, 3) qkv_gemm(
    const float* __restrict__ coords, const int* __restrict__ seq_idx,
    const float* __restrict__ qnw, const float* __restrict__ knw,
    const float* __restrict__ pfreqs)
{
    constexpr int CO = 256, CI = 64, BK = 64;
    constexpr int Ktot = G * CI;       // 768
    constexpr int NIT  = Ktot / BK;    // 12

    extern __shared__ __half smh[];
    __half* As = smh;                      // [2][128][HPAD]
    __half* Bs = smh + 2 * 128 * HPAD;     // [2][64][HPAD]

    const int prob = blockIdx.z;
    const __half* X = g_xh;
    const __half* W = (prob == 0) ? g_wqh : (prob == 1) ? g_wkh : g_wvh;

    const int tid = threadIdx.x;
    const int n0 = blockIdx.x * 64;
    const int t0 = blockIdx.y * 128;
    const int go = n0 / CO;
    const int o0 = n0 % CO;

    const int wid    = tid >> 5;
    const int lane   = tid & 31;
    const int warp_m = wid & 3;
    const int warp_n = wid >> 2;
    const int grp    = lane >> 2;
    const int qd     = lane & 3;

    // ldsm lane pieces: A (m-major) and B (n rows, k cols)
    const int a_lrow = lane & 15;
    const int a_lcol = (lane >> 4) * 8;
    const int b_row  = ((lane >> 4) & 1) * 8 + (lane & 7);
    const int b_dof  = ((lane >> 3) & 1) * 8;

    auto load_tile = [&](int buf, int kk) {
        const int gi = kk / CI;            // BK == CI -> i0 = 0
        const int wg = (gi - go + G) % G;
        const __half* Xb = X + (size_t)t0 * Ktot + kk;
        const __half* Wb = W + ((size_t)wg * CO + o0) * CI;
        __half* Ab = As + buf * 128 * HPAD;
        __half* Bb = Bs + buf * 64 * HPAD;
        #pragma unroll
        for (int i = 0; i < 4; i++) {           // A: 128 rows x 8 chunks
            const int ch  = tid + i * 256;
            const int row = ch >> 3;
            const int c8  = (ch & 7) << 3;
            cpa16(Ab + row * HPAD + c8, Xb + (size_t)row * Ktot + c8);
        }
        #pragma unroll
        for (int i = 0; i < 2; i++) {           // B: 64 rows x 8 chunks
            const int ch  = tid + i * 256;
            const int row = ch >> 3;
            const int c8  = (ch & 7) << 3;
            cpa16(Bb + row * HPAD + c8, Wb + (size_t)row * CI + c8);
        }
        asm volatile("cp.async.commit_group;");
    };

    float acc[2][4][4];
    #pragma unroll
    for (int mt = 0; mt < 2; mt++)
        #pragma unroll
        for (int nt = 0; nt < 4; nt++)
            #pragma unroll
            for (int i = 0; i < 4; i++) acc[mt][nt][i] = 0.0f;

    load_tile(0, 0);
    for (int it = 0; it < NIT; it++) {
        if (it + 1 < NIT) {
            load_tile((it + 1) & 1, (it + 1) * BK);
            asm volatile("cp.async.wait_group 1;");
        } else {
            asm volatile("cp.async.wait_group 0;");
        }
        __syncthreads();
        const __half* Ab = As + (it & 1) * 128 * HPAD;
        const __half* Bb = Bs + (it & 1) * 64 * HPAD;
        #pragma unroll
        for (int ks = 0; ks < 4; ks++) {        // 4 x k16
            const int kb = ks * 16;
            uint32_t a[2][4];
            #pragma unroll
            for (int mt = 0; mt < 2; mt++)
                ldsm4(a[mt][0], a[mt][1], a[mt][2], a[mt][3],
                      Ab + (warp_m * 32 + mt * 16 + a_lrow) * HPAD + kb + a_lcol);
            #pragma unroll
            for (int np = 0; np < 2; np++) {
                uint32_t r0, r1, r2, r3;
                ldsm4(r0, r1, r2, r3,
                      Bb + (warp_n * 32 + np * 16 + b_row) * HPAD + kb + b_dof);
                #pragma unroll
                for (int mt = 0; mt < 2; mt++) {
                    mma_f16(acc[mt][np * 2    ], a[mt], r0, r1);
                    mma_f16(acc[mt][np * 2 + 1], a[mt], r2, r3);
                }
            }
        }
        __syncthreads();
    }

    // ---- fused epilogue: this warp's 32 cols = head (go, h) ----
    const int h  = (o0 >> 5) + warp_n;
    const int gh = go * H + h;

    if (prob == 2) {
        #pragma unroll
        for (int mt = 0; mt < 2; mt++)
            #pragma unroll
            for (int rh = 0; rh < 2; rh++) {
                const int row = t0 + warp_m * 32 + mt * 16 + grp + rh * 8;
                const int bb = row >> 9, n = row & 511;
                const size_t rb = (((size_t)bb * GH + gh) * SEQ + n) * 32;
                #pragma unroll
                for (int nt = 0; nt < 4; nt++) {
                    const int d0 = nt * 8 + 2 * qd;
                    half2 hv = __floats2half2_rn(acc[mt][nt][2 * rh],
                                                 acc[mt][nt][2 * rh + 1]);
                    *(half2*)&g_vh[rb + d0] = hv;
                }
            }
        return;
    }

    const float* wt = (prob == 0) ? qnw : knw;
    float invf[4], fr0[4], fr1[4], fr2[4], w1[4], w2[4];
    #pragma unroll
    for (int nt = 0; nt < 4; nt++) {
        const int f = nt * 4 + qd;
        invf[nt] = __expf(-(float)f * LOG1E4_OV16);
        const float* fp = pfreqs + (h * 16 + f) * 3;
        fr0[nt] = fp[0];  fr1[nt] = fp[1];  fr2[nt] = fp[2];
        const int d0 = nt * 8 + 2 * qd;
        w1[nt] = wt[d0];  w2[nt] = wt[d0 + 1];
    }
    float sg, cg;
    __sincosf(6.283185307179586f * (float)go * (1.0f / 12.0f), &sg, &cg);

    #pragma unroll
    for (int mt = 0; mt < 2; mt++)
        #pragma unroll
        for (int rh = 0; rh < 2; rh++) {
            float ss = 0.0f;
            #pragma unroll
            for (int nt = 0; nt < 4; nt++) {
                float v1 = acc[mt][nt][2 * rh], v2 = acc[mt][nt][2 * rh + 1];
                ss += v1 * v1 + v2 * v2;
            }
            ss += __shfl_xor_sync(0xffffffffu, ss, 1);
            ss += __shfl_xor_sync(0xffffffffu, ss, 2);
            const float rn = rsqrtf(ss * (1.0f / 32.0f) + EPS);

            const int row = t0 + warp_m * 32 + mt * 16 + grp + rh * 8;
            const int bb = row >> 9, n = row & 511;
            const float pos = (float)seq_idx[row];
            const float cx = coords[row * 3 + 0];
            const float cy = coords[row * 3 + 1];
            const float cz = coords[row * 3 + 2];
            const float c0 =  cx * cg + cy * sg;
            const float c1 = -cx * sg + cy * cg;
            const size_t rb = (((size_t)bb * GH + gh) * SEQ + n) * 32;

            #pragma unroll
            for (int nt = 0; nt < 4; nt++) {
                const float v1 = acc[mt][nt][2 * rh] * rn * w1[nt];
                const float v2 = acc[mt][nt][2 * rh + 1] * rn * w2[nt];
                const float ang = pos * invf[nt]
                                + c0 * fr0[nt] + c1 * fr1[nt] + cz * fr2[nt];
                float s, c;  sincosf(ang, &s, &c);
                const float o1 = v1 * c - v2 * s;
                const float o2 = v1 * s + v2 * c;
                const int d0 = nt * 8 + 2 * qd;
                if (prob == 0) {
                    *(float2*)&g_qT[rb + d0] = make_float2(o1, o2);
                } else {
                    uint32_t hi, lo;
                    pack_hilo(o1, o2, hi, lo);
                    *(uint32_t*)&g_khi[rb + d0] = hi;
                    *(uint32_t*)&g_klo[rb + d0] = lo;
                }
            }
        }
}

// ---------------- Wo GEMM (fp16, split-K=4) ---------------------------------
__global__ void __launch_bounds__(256, 3) wo_gemm()
{
    constexpr int CO = 64, CI = 256, BK = 64;
    constexpr int Ktot = DQK;              // 3072
    constexpr int Kper = Ktot / 4;         // 768
    constexpr int NIT  = Kper / BK;        // 12
    constexpr int Ntot = DOUT;             // 768

    extern __shared__ __half smh[];
    __half* As = smh;
    __half* Bs = smh + 2 * 128 * HPAD;

    const int ksl = blockIdx.z;
    float* Y = g_part + (size_t)ksl * T_TOK * Ntot;

    const int tid = threadIdx.x;
    const int n0 = blockIdx.x * 64;
    const int t0 = blockIdx.y * 128;
    const int go = n0 / CO;

    const int wid    = tid >> 5;
    const int lane   = tid & 31;
    const int warp_m = wid & 3;
    const int warp_n = wid >> 2;
    const int grp    = lane >> 2;
    const int qd     = lane & 3;

    const int a_lrow = lane & 15;
    const int a_lcol = (lane >> 4) * 8;
    const int b_row  = ((lane >> 4) & 1) * 8 + (lane & 7);
    const int b_dof  = ((lane >> 3) & 1) * 8;

    auto load_tile = [&](int buf, int kk) {
        const int gi = kk / CI;
        const int i0 = kk % CI;
        const int wg = (gi - go + G) % G;
        const __half* Xb = g_aoh + (size_t)t0 * Ktot + kk;
        const __half* Wb = g_woh + ((size_t)wg * CO) * CI + i0;
        __half* Ab = As + buf * 128 * HPAD;
        __half* Bb = Bs + buf * 64 * HPAD;
        #pragma unroll
        for (int i = 0; i < 4; i++) {
            const int ch  = tid + i * 256;
            const int row = ch >> 3;
            const int c8  = (ch & 7) << 3;
            cpa16(Ab + row * HPAD + c8, Xb + (size_t)row * Ktot + c8);
        }
        #pragma unroll
        for (int i = 0; i < 2; i++) {
            const int ch  = tid + i * 256;
            const int row = ch >> 3;
            const int c8  = (ch & 7) << 3;
            cpa16(Bb + row * HPAD + c8, Wb + (size_t)row * CI + c8);
        }
        asm volatile("cp.async.commit_group;");
    };

    float acc[2][4][4];
    #pragma unroll
    for (int mt = 0; mt < 2; mt++)
        #pragma unroll
        for (int nt = 0; nt < 4; nt++)
            #pragma unroll
            for (int i = 0; i < 4; i++) acc[mt][nt][i] = 0.0f;

    const int kbeg = ksl * Kper;
    load_tile(0, kbeg);
    for (int it = 0; it < NIT; it++) {
        if (it + 1 < NIT) {
            load_tile((it + 1) & 1, kbeg + (it + 1) * BK);
            asm volatile("cp.async.wait_group 1;");
        } else {
            asm volatile("cp.async.wait_group 0;");
        }
        __syncthreads();
        const __half* Ab = As + (it & 1) * 128 * HPAD;
        const __half* Bb = Bs + (it & 1) * 64 * HPAD;
        #pragma unroll
        for (int ks = 0; ks < 4; ks++) {
            const int kb = ks * 16;
            uint32_t a[2][4];
            #pragma unroll
            for (int mt = 0; mt < 2; mt++)
                ldsm4(a[mt][0], a[mt][1], a[mt][2], a[mt][3],
                      Ab + (warp_m * 32 + mt * 16 + a_lrow) * HPAD + kb + a_lcol);
            #pragma unroll
            for (int np = 0; np < 2; np++) {
                uint32_t r0, r1, r2, r3;
                ldsm4(r0, r1, r2, r3,
                      Bb + (warp_n * 32 + np * 16 + b_row) * HPAD + kb + b_dof);
                #pragma unroll
                for (int mt = 0; mt < 2; mt++) {
                    mma_f16(acc[mt][np * 2    ], a[mt], r0, r1);
                    mma_f16(acc[mt][np * 2 + 1], a[mt], r2, r3);
                }
            }
        }
        __syncthreads();
    }

    #pragma unroll
    for (int mt = 0; mt < 2; mt++) {
        const int trow = t0 + warp_m * 32 + mt * 16 + grp;
        #pragma unroll
        for (int nt = 0; nt < 4; nt++) {
            const int ncol = n0 + warp_n * 32 + nt * 8 + 2 * qd;
            *(float2*)&Y[(size_t)trow * Ntot + ncol] =
                make_float2(acc[mt][nt][0], acc[mt][nt][1]);
            *(float2*)&Y[(size_t)(trow + 8) * Ntot + ncol] =
                make_float2(acc[mt][nt][2], acc[mt][nt][3]);
        }
    }
}

// ---------------- split-K reduce -------------------------------------------
__global__ void __launch_bounds__(256) reduce4_kernel(float* __restrict__ out)
{
    const int i = blockIdx.x * 256 + threadIdx.x;
    const size_t S = (size_t)T_TOK * DOUT / 4;
    const float4* p = (const float4*)g_part;
    float4 a = p[i], b = p[i + S], c = p[i + 2 * S], d = p[i + 3 * S];
    float4 r;
    r.x = (a.x + b.x) + (c.x + d.x);
    r.y = (a.y + b.y) + (c.y + d.y);
    r.z = (a.z + b.z) + (c.z + d.z);
    r.w = (a.w + b.w) + (c.w + d.w);
    ((float4*)out)[i] = r;
}

// ---------------- attention: 512 threads, 16-query warps --------------------
// fp16 hi/lo QK^T (3-term) + fp16 PV (P hi only).
#define KPH 40   // half row stride (80 B rows, ldsm conflict-free)
#define ATTN_SMEM (3 * 512 * KPH * 2)   // 122880 B

__global__ void __launch_bounds__(512) attn_mma_kernel()
{
    extern __shared__ __half sh_h[];
    __half* Khi = sh_h;                 // [512][KPH]
    __half* Klo = sh_h + 512 * KPH;
    __half* Vs  = sh_h + 2 * 512 * KPH;

    const int qc = blockIdx.x;   // 0..1
    const int gh = blockIdx.y;
    const int b  = blockIdx.z;
    const int tid  = threadIdx.x;
    const int wid  = tid >> 5;   // 0..15
    const int lane = tid & 31;
    const int grp  = lane >> 2;
    const int qd   = lane & 3;

    const size_t base = ((size_t)b * GH + gh) * SEQ * 32;

    // ---- prologue: pure cp.async copy ----
    #pragma unroll
    for (int i = 0; i < 4; i++) {
        const int ch  = tid + i * 512;
        const int row = ch >> 2;
        const int c   = (ch & 3) * 8;
        cpa16(Khi + row * KPH + c, g_khi + base + row * 32 + c);
        cpa16(Klo + row * KPH + c, g_klo + base + row * 32 + c);
        cpa16(Vs  + row * KPH + c, g_vh  + base + row * 32 + c);
    }
    asm volatile("cp.async.commit_group;");

    // ---- Q fragments (fp16 hi/lo, scale folded) ----
    const int qrow0 = qc * 256 + wid * 16;
    const float scale = 0.17677669529663687f;   // 1/sqrt(32)
    uint32_t qhi[2][4], qlo[2][4];
    #pragma unroll
    for (int kh = 0; kh < 2; kh++)
        #pragma unroll
        for (int e = 0; e < 4; e++) {
            const int row = grp + (e & 1) * 8;
            const int col = kh * 16 + 2 * qd + (e >> 1) * 8;
            const float* qp = g_qT + base + (size_t)(qrow0 + row) * 32 + col;
            pack_hilo(qp[0] * scale, qp[1] * scale, qhi[kh][e], qlo[kh][e]);
        }

    asm volatile("cp.async.wait_group 0;");
    __syncthreads();

    float mrow[2] = {-1e30f, -1e30f}, lrow[2] = {0.0f, 0.0f};
    float o[4][4];
    #pragma unroll
    for (int nt = 0; nt < 4; nt++)
        #pragma unroll
        for (int c = 0; c < 4; c++) o[nt][c] = 0.0f;

    const int k_key = ((lane >> 4) & 1) * 8 + (lane & 7);
    const int k_dof = ((lane >> 3) & 1) * 8;
    const int v_key = ((lane >> 3) & 1) * 8 + (lane & 7);
    const int v_dof = ((lane >> 4) & 1) * 8;

    float s[8][4];

    for (int kt = 0; kt < 8; kt++) {        // 8 key tiles of 64
        #pragma unroll
        for (int nt = 0; nt < 8; nt++)
            #pragma unroll
            for (int c = 0; c < 4; c++) s[nt][c] = 0.0f;

        // ---- QK^T: fp16 hi/lo 3-term ----
        #pragma unroll
        for (int kh = 0; kh < 2; kh++) {
            const int dh = kh * 16;
            #pragma unroll
            for (int jp = 0; jp < 4; jp++) {
                const int kb = kt * 64 + jp * 16;
                uint32_t h0, h1, h2, h3, l0, l1, l2, l3;
                ldsm4(h0, h1, h2, h3, Khi + (kb + k_key) * KPH + dh + k_dof);
                ldsm4(l0, l1, l2, l3, Klo + (kb + k_key) * KPH + dh + k_dof);
                mma_f16(s[jp * 2    ], qhi[kh], h0, h1);
                mma_f16(s[jp * 2    ], qhi[kh], l0, l1);
                mma_f16(s[jp * 2    ], qlo[kh], h0, h1);
                mma_f16(s[jp * 2 + 1], qhi[kh], h2, h3);
                mma_f16(s[jp * 2 + 1], qhi[kh], l2, l3);
                mma_f16(s[jp * 2 + 1], qlo[kh], h2, h3);
            }
        }

        // ---- online softmax ----
        float esc[2];
        #pragma unroll
        for (int hh = 0; hh < 2; hh++) {
            float mx = -1e30f;
            #pragma unroll
            for (int nt = 0; nt < 8; nt++)
                mx = fmaxf(mx, fmaxf(s[nt][2 * hh], s[nt][2 * hh + 1]));
            mx = fmaxf(mx, __shfl_xor_sync(0xffffffffu, mx, 1));
            mx = fmaxf(mx, __shfl_xor_sync(0xffffffffu, mx, 2));
            const float mnew = fmaxf(mrow[hh], mx);
            esc[hh] = __expf(mrow[hh] - mnew);
            mrow[hh] = mnew;
        }
        #pragma unroll
        for (int nt = 0; nt < 8; nt++)
            #pragma unroll
            for (int c = 0; c < 4; c++)
                s[nt][c] = __expf(s[nt][c] - mrow[c >> 1]);
        #pragma unroll
        for (int hh = 0; hh < 2; hh++) {
            float ps = 0.0f;
            #pragma unroll
            for (int nt = 0; nt < 8; nt++)
                ps += s[nt][2 * hh] + s[nt][2 * hh + 1];
            ps += __shfl_xor_sync(0xffffffffu, ps, 1);
            ps += __shfl_xor_sync(0xffffffffu, ps, 2);
            lrow[hh] = lrow[hh] * esc[hh] + ps;
        }
        #pragma unroll
        for (int nt = 0; nt < 4; nt++)
            #pragma unroll
            for (int c = 0; c < 4; c++)
                o[nt][c] *= esc[c >> 1];

        // ---- P·V: fp16 m16n8k16, P hi only, V frags via ldmatrix.trans ----
        #pragma unroll
        for (int j = 0; j < 4; j++) {
            const int kb = kt * 64 + j * 16;
            uint32_t vb[4][2];
            #pragma unroll
            for (int dv = 0; dv < 2; dv++) {
                uint32_t r0, r1, r2, r3;
                ldsm4t(r0, r1, r2, r3, Vs + (kb + v_key) * KPH + dv * 16 + v_dof);
                vb[dv * 2    ][0] = r0;  vb[dv * 2    ][1] = r1;
                vb[dv * 2 + 1][0] = r2;  vb[dv * 2 + 1][1] = r3;
            }
            uint32_t ah[4];
            ah[0] = packh2(s[2*j  ][0], s[2*j  ][1]);
            ah[1] = packh2(s[2*j  ][2], s[2*j  ][3]);
            ah[2] = packh2(s[2*j+1][0], s[2*j+1][1]);
            ah[3] = packh2(s[2*j+1][2], s[2*j+1][3]);
            #pragma unroll
            for (int nt = 0; nt < 4; nt++)
                mma_f16(o[nt], ah, vb[nt][0], vb[nt][1]);
        }
    }

    // ---- epilogue: write fp16 directly for the Wo GEMM ----
    const float inv0 = 1.0f / lrow[0];
    const float inv1 = 1.0f / lrow[1];
    const int n0 = qrow0 + grp;
    #pragma unroll
    for (int nt = 0; nt < 4; nt++) {
        const int gcol = gh * 32 + nt * 8 + 2 * qd;
        *(uint32_t*)&g_aoh[((size_t)(b * SEQ + n0)) * DQK + gcol] =
            packh2(o[nt][0] * inv0, o[nt][1] * inv0);
        *(uint32_t*)&g_aoh[((size_t)(b * SEQ + n0 + 8)) * DQK + gcol] =
            packh2(o[nt][2] * inv1, o[nt][3] * inv1);
    }
}

// ---------------- launch ---------------------------------------------------
extern "C" void kernel_launch(void* const* d_in, const int* in_sizes, int n_in,
                              void* d_out, int out_size)
{
    const float* feat   = (const float*)d_in[0];
    const float* coords = (const float*)d_in[1];
    const float* Wq     = (const float*)d_in[2];
    const float* Wk     = (const float*)d_in[3];
    const float* Wv     = (const float*)d_in[4];
    const float* Wo     = (const float*)d_in[5];
    const float* qnw    = (const float*)d_in[6];
    const float* knw    = (const float*)d_in[7];
    const float* pfrq   = (const float*)d_in[8];
    const int*   sidx   = (const int*)d_in[9];
    float* out = (float*)d_out;

    cudaFuncSetAttribute(qkv_gemm,
                         cudaFuncAttributeMaxDynamicSharedMemorySize, GEMM_SMEM);
    cudaFuncSetAttribute(wo_gemm,
                         cudaFuncAttributeMaxDynamicSharedMemorySize, GEMM_SMEM);
    cudaFuncSetAttribute(attn_mma_kernel,
                         cudaFuncAttributeMaxDynamicSharedMemorySize, ATTN_SMEM);

    // convert inputs to fp16
    half_prep<<<PREP_T / 256, 256>>>(feat, Wq, Wk, Wv, Wo);

    // QKV projections with fused rms_norm + ropes + layout conversion
    qkv_gemm<<<dim3(DQK / 64, T_TOK / 128, 3), 256, GEMM_SMEM>>>(
        coords, sidx, qnw, knw, pfrq);

    // attention
    attn_mma_kernel<<<dim3(2, GH, BATCH), 512, ATTN_SMEM>>>();

    // output projection, split-K=4 + reduce
    wo_gemm<<<dim3(DOUT / 64, T_TOK / 128, 4), 256, GEMM_SMEM>>>();
    reduce4_kernel<<<T_TOK * DOUT / 4 / 256, 256>>>(out);
}